// round 11
// baseline (speedup 1.0000x reference)
#include <cuda_runtime.h>
#include <cuda_bf16.h>
#include <math.h>
#include <cstdint>

#define NTOK 9216
#define BATCH 4
#define CHN 256
#define HEADS 8
#define DH 32
#define NB 128
#define BH (BATCH*HEADS)
#define MTOT (BATCH*NTOK)

#define DN 0.4204482076268573f
#define HALF_DN2 0.08838834764831845f
#define RATIO 0.08838834764831845f
#define FEPS 1e-4f

static __device__ float d_ctxe[(size_t)BH*128*33];  // [bh][feat][0..31=ctx, 32=ksum]
static __device__ float d_vsum[BH*DH];
static __device__ float d_xsum[BATCH*CHN];
static __device__ float d_kmax[BH];
static __device__ float d_bcomb[CHN];
static __device__ float d_diagq[(size_t)MTOT*HEADS];
static __device__ float d_diagk[(size_t)MTOT*HEADS];

static __device__ __nv_bfloat16 d_xth[(size_t)MTOT*CHN];
static __device__ __nv_bfloat16 d_xtl[(size_t)MTOT*CHN];
static __device__ __nv_bfloat16 d_w3h[3*CHN*CHN];
static __device__ __nv_bfloat16 d_w3l[3*CHN*CHN];
static __device__ __nv_bfloat16 d_qh[(size_t)MTOT*CHN];
static __device__ __nv_bfloat16 d_ql[(size_t)MTOT*CHN];
static __device__ __nv_bfloat16 d_kh[(size_t)MTOT*CHN];
static __device__ __nv_bfloat16 d_kl[(size_t)MTOT*CHN];
static __device__ __nv_bfloat16 d_vh[(size_t)MTOT*CHN];
static __device__ __nv_bfloat16 d_vl[(size_t)MTOT*CHN];
static __device__ __nv_bfloat16 d_ath[(size_t)MTOT*CHN];
static __device__ __nv_bfloat16 d_atl[(size_t)MTOT*CHN];
static __device__ __nv_bfloat16 d_wch[CHN*CHN];
static __device__ __nv_bfloat16 d_wcl[CHN*CHN];
static __device__ __nv_bfloat16 d_ctxTh[BH*40*128];  // [bh][row 0..31=ctx_d, 32=ksum, 33..39=0][feat]
static __device__ __nv_bfloat16 d_ctxTl[BH*40*128];

// ---- mma helpers ----
__device__ __forceinline__ uint32_t smem_u32(const void* p) {
    uint32_t a;
    asm("{ .reg .u64 t; cvta.to.shared.u64 t, %1; cvt.u32.u64 %0, t; }" : "=r"(a) : "l"(p));
    return a;
}
__device__ __forceinline__ void ldsm_x4(uint32_t* r, uint32_t addr) {
    asm volatile("ldmatrix.sync.aligned.m8n8.x4.shared.b16 {%0,%1,%2,%3}, [%4];"
        : "=r"(r[0]), "=r"(r[1]), "=r"(r[2]), "=r"(r[3]) : "r"(addr));
}
__device__ __forceinline__ void ldsm_x2(uint32_t* r, uint32_t addr) {
    asm volatile("ldmatrix.sync.aligned.m8n8.x2.shared.b16 {%0,%1}, [%2];"
        : "=r"(r[0]), "=r"(r[1]) : "r"(addr));
}
__device__ __forceinline__ void ldsm_x4_t(uint32_t* r, uint32_t addr) {
    asm volatile("ldmatrix.sync.aligned.m8n8.x4.trans.shared.b16 {%0,%1,%2,%3}, [%4];"
        : "=r"(r[0]), "=r"(r[1]), "=r"(r[2]), "=r"(r[3]) : "r"(addr));
}
__device__ __forceinline__ void ldsm_x2_t(uint32_t* r, uint32_t addr) {
    asm volatile("ldmatrix.sync.aligned.m8n8.x2.trans.shared.b16 {%0,%1}, [%2];"
        : "=r"(r[0]), "=r"(r[1]) : "r"(addr));
}
__device__ __forceinline__ void mma16816(float* c, const uint32_t* a, const uint32_t* b) {
    asm volatile("mma.sync.aligned.m16n8k16.row.col.f32.bf16.bf16.f32 "
        "{%0,%1,%2,%3}, {%4,%5,%6,%7}, {%8,%9}, {%0,%1,%2,%3};"
        : "+f"(c[0]), "+f"(c[1]), "+f"(c[2]), "+f"(c[3])
        : "r"(a[0]), "r"(a[1]), "r"(a[2]), "r"(a[3]), "r"(b[0]), "r"(b[1]));
}
__device__ __forceinline__ void atomicMaxFloat(float* addr, float val) {
    int* ai = (int*)addr;
    int old = __float_as_int(*addr);
    while (__int_as_float(old) < val) {
        int assumed = old;
        old = atomicCAS(ai, assumed, __float_as_int(val));
        if (old == assumed) break;
    }
}
__device__ __forceinline__ void split_bf16(float v, __nv_bfloat16& h, __nv_bfloat16& l) {
    h = __float2bfloat16_rn(v);
    l = __float2bfloat16_rn(v - __bfloat162float(h));
}
__device__ __forceinline__ void split2pack(float a, float b, uint32_t& hi, uint32_t& lo) {
    __nv_bfloat16 ha = __float2bfloat16_rn(a);
    __nv_bfloat16 hb = __float2bfloat16_rn(b);
    __nv_bfloat16 la = __float2bfloat16_rn(a - __bfloat162float(ha));
    __nv_bfloat16 lb = __float2bfloat16_rn(b - __bfloat162float(hb));
    hi = (uint32_t)(*(unsigned short*)&ha) | ((uint32_t)(*(unsigned short*)&hb) << 16);
    lo = (uint32_t)(*(unsigned short*)&la) | ((uint32_t)(*(unsigned short*)&lb) << 16);
}

// ---------------------------------------------------------------------------
__global__ void init_k() {
    int i = blockIdx.x * 256 + threadIdx.x;
    if (i < BH*128*33) d_ctxe[i] = 0.0f;
    if (i < BATCH*CHN) d_xsum[i] = 0.0f;
    if (i < BH)        d_kmax[i] = -INFINITY;
}

__global__ __launch_bounds__(256) void conv_w(const float* __restrict__ wq,
                                              const float* __restrict__ wk,
                                              const float* __restrict__ wv) {
    int z = blockIdx.y, o = blockIdx.x, c = threadIdx.x;
    const float* W = (z == 0) ? wq : ((z == 1) ? wk : wv);
    float v = W[o*CHN + c];
    __nv_bfloat16 h, l; split_bf16(v, h, l);
    d_w3h[(z*CHN + o)*CHN + c] = h;
    d_w3l[(z*CHN + o)*CHN + c] = l;
}

__global__ __launch_bounds__(256) void wcomb_k(const float* __restrict__ wo,
                                               const float* __restrict__ bo,
                                               const float* __restrict__ wp,
                                               const float* __restrict__ bp) {
    int o = blockIdx.x, c = threadIdx.x;
    float acc = 0.0f;
    for (int j = 0; j < CHN; j++) acc += wp[o*CHN + j] * wo[j*CHN + c];
    __nv_bfloat16 h, l; split_bf16(acc, h, l);
    d_wch[o*CHN + c] = h;
    d_wcl[o*CHN + c] = l;
    if (c == 0) {
        float bcc = 0.0f;
        for (int j = 0; j < CHN; j++) bcc += wp[o*CHN + j] * bo[j];
        d_bcomb[o] = bcc + bp[o];
    }
}

// ---------------------------------------------------------------------------
// transpose x -> bf16 hi/lo + accumulate xsum[b][c]
// ---------------------------------------------------------------------------
__global__ __launch_bounds__(256) void xt_k(const float* __restrict__ x) {
    __shared__ float ts[32][33];
    int b = blockIdx.z, c0 = blockIdx.y * 32, p0 = blockIdx.x * 32;
    int tid = threadIdx.x;
    int tx = tid & 31, ty = tid >> 5;
    #pragma unroll
    for (int i = 0; i < 4; i++) {
        int c = c0 + ty + i*8;
        ts[ty + i*8][tx] = x[((size_t)(b*CHN + c))*NTOK + p0 + tx];
    }
    __syncthreads();
    {
        int cl = tid >> 3, j0 = (tid & 7)*4;
        float s = ts[cl][j0] + ts[cl][j0+1] + ts[cl][j0+2] + ts[cl][j0+3];
        s += __shfl_xor_sync(0xffffffffu, s, 1);
        s += __shfl_xor_sync(0xffffffffu, s, 2);
        s += __shfl_xor_sync(0xffffffffu, s, 4);
        if ((tid & 7) == 0) atomicAdd(&d_xsum[b*CHN + c0 + cl], s);
    }
    #pragma unroll
    for (int i = 0; i < 4; i++) {
        int p = p0 + ty + i*8;
        float v = ts[tx][ty + i*8];
        size_t gi = (size_t)(b*NTOK + p)*CHN + c0 + tx;
        __nv_bfloat16 h, l; split_bf16(v, h, l);
        d_xth[gi] = h;
        d_xtl[gi] = l;
    }
}

__global__ __launch_bounds__(32) void vsum_k(const float* __restrict__ wv) {
    int bh = blockIdx.x, d = threadIdx.x;
    int b = bh >> 3, hd = bh & 7;
    const float* xs = &d_xsum[b*CHN];
    const float* wr = &wv[(hd*32 + d)*CHN];
    float s = 0.0f;
    for (int c = 0; c < CHN; c++) s += xs[c]*wr[c];
    d_vsum[bh*32 + d] = s;
}

// ---------------------------------------------------------------------------
// QKV GEMM via mma.sync -> bf16 hi/lo outputs + per-token per-head diag
// ---------------------------------------------------------------------------
__global__ __launch_bounds__(256) void qkv_mms() {
    __shared__ __align__(16) __nv_bfloat16 Ah[128][40];
    __shared__ __align__(16) __nv_bfloat16 Al[128][40];
    __shared__ __align__(16) __nv_bfloat16 Bh[64][40];
    __shared__ __align__(16) __nv_bfloat16 Bl[64][40];

    int z = blockIdx.z;
    const __nv_bfloat16* WH = d_w3h + (size_t)z*CHN*CHN;
    const __nv_bfloat16* WL = d_w3l + (size_t)z*CHN*CHN;
    __nv_bfloat16* CH = (z == 0) ? d_qh : ((z == 1) ? d_kh : d_vh);
    __nv_bfloat16* CL = (z == 0) ? d_ql : ((z == 1) ? d_kl : d_vl);
    int m0 = blockIdx.x * 128, n0 = blockIdx.y * 64;
    int tid = threadIdx.x, wid = tid >> 5, lane = tid & 31;
    int wm = (wid & 3) * 32, wn = (wid >> 2) * 32;

    float acc[2][4][4];
    #pragma unroll
    for (int mi = 0; mi < 2; mi++)
        #pragma unroll
        for (int ni = 0; ni < 4; ni++)
            #pragma unroll
            for (int q = 0; q < 4; q++) acc[mi][ni][q] = 0.0f;

    int arow = wm + (lane & 15);
    int acol8 = (lane >> 4) * 8;
    int brow = wn + ((lane >> 4) << 3) + (lane & 7);
    int bcol8 = ((lane >> 3) & 1) * 8;

    for (int ck = 0; ck < 8; ck++) {
        int k0 = ck * 32;
        #pragma unroll
        for (int j = 0; j < 2; j++) {
            int i = tid + j*256, row = i >> 2, cg = i & 3;
            size_t g = (size_t)(m0 + row)*CHN + k0 + cg*8;
            *(uint4*)&Ah[row][cg*8] = *(const uint4*)(d_xth + g);
            *(uint4*)&Al[row][cg*8] = *(const uint4*)(d_xtl + g);
        }
        {
            int row = tid >> 2, cg = tid & 3;
            size_t g = (size_t)(n0 + row)*CHN + k0 + cg*8;
            *(uint4*)&Bh[row][cg*8] = *(const uint4*)(WH + g);
            *(uint4*)&Bl[row][cg*8] = *(const uint4*)(WL + g);
        }
        __syncthreads();
        #pragma unroll
        for (int ks = 0; ks < 32; ks += 16) {
            uint32_t ah[2][4], al[2][4], bh[2][4], bl[2][4];
            #pragma unroll
            for (int mi = 0; mi < 2; mi++) {
                ldsm_x4(ah[mi], smem_u32(&Ah[arow + mi*16][ks + acol8]));
                ldsm_x4(al[mi], smem_u32(&Al[arow + mi*16][ks + acol8]));
            }
            #pragma unroll
            for (int p = 0; p < 2; p++) {
                ldsm_x4(bh[p], smem_u32(&Bh[brow + p*16][ks + bcol8]));
                ldsm_x4(bl[p], smem_u32(&Bl[brow + p*16][ks + bcol8]));
            }
            #pragma unroll
            for (int mi = 0; mi < 2; mi++)
                #pragma unroll
                for (int ni = 0; ni < 4; ni++) {
                    const uint32_t* bhp = &bh[ni >> 1][(ni & 1)*2];
                    const uint32_t* blp = &bl[ni >> 1][(ni & 1)*2];
                    mma16816(acc[mi][ni], ah[mi], bhp);
                    mma16816(acc[mi][ni], ah[mi], blp);
                    mma16816(acc[mi][ni], al[mi], bhp);
                }
        }
        __syncthreads();
    }
    int hd2 = (n0 + wn) >> 5;  // warp's 32-col n-range = one head
    #pragma unroll
    for (int mi = 0; mi < 2; mi++) {
        float ds0 = 0.0f, ds1 = 0.0f;
        int m = m0 + wm + mi*16 + (lane >> 2);
        #pragma unroll
        for (int ni = 0; ni < 4; ni++) {
            int n = n0 + wn + ni*8 + 2*(lane & 3);
            uint32_t h0, l0, h1, l1;
            split2pack(acc[mi][ni][0], acc[mi][ni][1], h0, l0);
            split2pack(acc[mi][ni][2], acc[mi][ni][3], h1, l1);
            *(uint32_t*)(CH + (size_t)m*CHN + n)     = h0;
            *(uint32_t*)(CL + (size_t)m*CHN + n)     = l0;
            *(uint32_t*)(CH + (size_t)(m+8)*CHN + n) = h1;
            *(uint32_t*)(CL + (size_t)(m+8)*CHN + n) = l1;
            ds0 += acc[mi][ni][0]*acc[mi][ni][0] + acc[mi][ni][1]*acc[mi][ni][1];
            ds1 += acc[mi][ni][2]*acc[mi][ni][2] + acc[mi][ni][3]*acc[mi][ni][3];
        }
        if (z < 2) {
            ds0 += __shfl_xor_sync(0xffffffffu, ds0, 1);
            ds0 += __shfl_xor_sync(0xffffffffu, ds0, 2);
            ds1 += __shfl_xor_sync(0xffffffffu, ds1, 1);
            ds1 += __shfl_xor_sync(0xffffffffu, ds1, 2);
            if ((lane & 3) == 0) {
                float* DD = (z == 0) ? d_diagq : d_diagk;
                DD[(size_t)m*HEADS + hd2]     = ds0 * HALF_DN2;
                DD[(size_t)(m+8)*HEADS + hd2] = ds1 * HALF_DN2;
            }
        }
    }
}

// ---------------------------------------------------------------------------
// k path via mma.sync: loaders are pure copies (bf16 hi/lo prepacked + diag).
// ---------------------------------------------------------------------------
__global__ __launch_bounds__(256, 2) void k_mms(const float* __restrict__ proj) {
    extern __shared__ char sm[];
    const int PH=0, PL=10240, VH=20480, VL=30720,
              EH=40960, EL=75776,           // E: [40960, 110592)
              KH=40960, KL=51200,           // K aliased inside E
              DG=110592, RED=111104;
    uint32_t sb = smem_u32(sm);
    int bh = blockIdx.y, chunk = blockIdx.x;
    int b = bh >> 3, hd = bh & 7;
    int tid = threadIdx.x, wid = tid >> 5, lane = tid & 31;
    int lrow = tid >> 1, lhalf = tid & 1;
    int wtok = wid * 16, wf = wid * 16;

    {
        const float4* p4 = (const float4*)(proj + lrow*32 + lhalf*16);
        #pragma unroll
        for (int i = 0; i < 4; i++) {
            float4 f = p4[i];
            uint32_t h0, l0, h1, l1;
            split2pack(f.x, f.y, h0, l0);
            split2pack(f.z, f.w, h1, l1);
            int co = lrow*80 + lhalf*32 + i*8;
            *(uint2*)(sm + PH + co) = make_uint2(h0, h1);
            *(uint2*)(sm + PL + co) = make_uint2(l0, l1);
        }
    }

    float lmax = -INFINITY;
    float acc2[5][4];
    #pragma unroll
    for (int i = 0; i < 5; i++)
        #pragma unroll
        for (int j = 0; j < 4; j++) acc2[i][j] = 0.0f;

    for (int tile = 0; tile < 9; tile++) {
        int p0 = chunk*1152 + tile*128;
        {
            size_t g = ((size_t)(b*NTOK + p0 + lrow))*CHN + hd*32 + lhalf*16;
            int co = lrow*80 + lhalf*32;
            *(uint4*)(sm + KH + co)      = *(const uint4*)(d_kh + g);
            *(uint4*)(sm + KH + co + 16) = *(const uint4*)(d_kh + g + 8);
            *(uint4*)(sm + KL + co)      = *(const uint4*)(d_kl + g);
            *(uint4*)(sm + KL + co + 16) = *(const uint4*)(d_kl + g + 8);
            *(uint4*)(sm + VH + co)      = *(const uint4*)(d_vh + g);
            *(uint4*)(sm + VH + co + 16) = *(const uint4*)(d_vh + g + 8);
            *(uint4*)(sm + VL + co)      = *(const uint4*)(d_vl + g);
            *(uint4*)(sm + VL + co + 16) = *(const uint4*)(d_vl + g + 8);
            if (lhalf == 0) {
                ((float*)(sm + DG))[lrow] = d_diagk[(size_t)(b*NTOK + p0 + lrow)*HEADS + hd];
            } else {
                *(uint4*)(sm + VH + lrow*80 + 64) = make_uint4(0x00003F80u, 0u, 0u, 0u);
                *(uint4*)(sm + VL + lrow*80 + 64) = make_uint4(0u, 0u, 0u, 0u);
            }
        }
        __syncthreads();

        float acc1[16][4];
        #pragma unroll
        for (int i = 0; i < 16; i++)
            #pragma unroll
            for (int j = 0; j < 4; j++) acc1[i][j] = 0.0f;
        #pragma unroll
        for (int ks = 0; ks < 32; ks += 16) {
            uint32_t ah[4], al[4];
            uint32_t aa = sb + KH + (wtok + (lane & 15))*80 + (ks + ((lane >> 4) << 3))*2;
            ldsm_x4(ah, aa);
            ldsm_x4(al, aa + (KL - KH));
            #pragma unroll
            for (int g = 0; g < 8; g++) {
                uint32_t bhf[4], blf[4];
                uint32_t ba = sb + PH + (g*16 + ((lane >> 4) << 3) + (lane & 7))*80
                                      + (ks + (((lane >> 3) & 1) << 3))*2;
                ldsm_x4(bhf, ba);
                ldsm_x4(blf, ba + (PL - PH));
                #pragma unroll
                for (int h = 0; h < 2; h++) {
                    float* c = acc1[g*2 + h];
                    mma16816(c, ah, &bhf[h*2]);
                    mma16816(c, ah, &blf[h*2]);
                    mma16816(c, al, &bhf[h*2]);
                }
            }
        }
        __syncthreads();   // all warps done reading K before E overwrites it
        {
            int r0 = wtok + (lane >> 2), cq = 2*(lane & 3);
            float dg0 = ((float*)(sm + DG))[r0];
            float dg1 = ((float*)(sm + DG))[r0 + 8];
            #pragma unroll
            for (int f = 0; f < 16; f++) {
                int c0 = f*8 + cq;
                float v0 = acc1[f][0]*DN, v1 = acc1[f][1]*DN;
                float v2 = acc1[f][2]*DN, v3 = acc1[f][3]*DN;
                lmax = fmaxf(lmax, fmaxf(fmaxf(v0, v1), fmaxf(v2, v3)));
                uint32_t h0, l0, h1, l1;
                split2pack(__expf(v0 - dg0), __expf(v1 - dg0), h0, l0);
                split2pack(__expf(v2 - dg1), __expf(v3 - dg1), h1, l1);
                *(uint32_t*)(sm + EH + r0*272 + c0*2)       = h0;
                *(uint32_t*)(sm + EL + r0*272 + c0*2)       = l0;
                *(uint32_t*)(sm + EH + (r0 + 8)*272 + c0*2) = h1;
                *(uint32_t*)(sm + EL + (r0 + 8)*272 + c0*2) = l1;
            }
        }
        __syncthreads();

        #pragma unroll
        for (int kk = 0; kk < 8; kk++) {
            int tok0 = kk*16;
            uint32_t eh[4], el[4];
            uint32_t aa = sb + EH + (tok0 + ((lane >> 4) << 3) + (lane & 7))*272
                                  + (wf + (((lane >> 3) & 1) << 3))*2;
            ldsm_x4_t(eh, aa);
            ldsm_x4_t(el, aa + (EL - EH));
            uint32_t vrowb = sb + VH + (tok0 + (((lane >> 3) & 1) << 3) + (lane & 7))*80;
            uint32_t doff = ((lane >> 4) << 3)*2;
            uint32_t vh0[4], vl0[4], vh1[4], vl1[4], v2h[2], v2l[2];
            ldsm_x4_t(vh0, vrowb + doff);
            ldsm_x4_t(vl0, vrowb + (VL - VH) + doff);
            ldsm_x4_t(vh1, vrowb + 32 + doff);
            ldsm_x4_t(vl1, vrowb + (VL - VH) + 32 + doff);
            ldsm_x2_t(v2h, vrowb + 64);
            ldsm_x2_t(v2l, vrowb + (VL - VH) + 64);
            const uint32_t* bhf[5] = {&vh0[0], &vh0[2], &vh1[0], &vh1[2], &v2h[0]};
            const uint32_t* blf[5] = {&vl0[0], &vl0[2], &vl1[0], &vl1[2], &v2l[0]};
            #pragma unroll
            for (int nf = 0; nf < 5; nf++) {
                mma16816(acc2[nf], eh, bhf[nf]);
                mma16816(acc2[nf], eh, blf[nf]);
                mma16816(acc2[nf], el, bhf[nf]);
            }
        }
        __syncthreads();
    }

    #pragma unroll
    for (int off = 16; off > 0; off >>= 1)
        lmax = fmaxf(lmax, __shfl_xor_sync(0xffffffffu, lmax, off));
    if (lane == 0) ((float*)(sm + RED))[wid] = lmax;
    __syncthreads();
    if (tid == 0) {
        float m = ((float*)(sm + RED))[0];
        #pragma unroll
        for (int i = 1; i < 8; i++) m = fmaxf(m, ((float*)(sm + RED))[i]);
        atomicMaxFloat(&d_kmax[bh], m);
    }
    {
        int r0 = wf + (lane >> 2), cq = 2*(lane & 3);
        #pragma unroll
        for (int nf = 0; nf < 4; nf++) {
            int c0 = nf*8 + cq;
            float* pa = &d_ctxe[((size_t)bh*128 + r0)*33 + c0];
            float* pb = &d_ctxe[((size_t)bh*128 + r0 + 8)*33 + c0];
            atomicAdd(pa,     acc2[nf][0]); atomicAdd(pa + 1, acc2[nf][1]);
            atomicAdd(pb,     acc2[nf][2]); atomicAdd(pb + 1, acc2[nf][3]);
        }
        if ((lane & 3) == 0) {
            atomicAdd(&d_ctxe[((size_t)bh*128 + r0)*33 + 32],     acc2[4][0]);
            atomicAdd(&d_ctxe[((size_t)bh*128 + r0 + 8)*33 + 32], acc2[4][2]);
        }
    }
}

// ---------------------------------------------------------------------------
// finalize -> transposed augmented ctxT bf16 hi/lo
// ---------------------------------------------------------------------------
__global__ __launch_bounds__(128) void k_final() {
    int bh = blockIdx.x, t = threadIdx.x;  // t = feat
    float scale = __expf(-d_kmax[bh]);
    const float* ce = &d_ctxe[((size_t)bh*128 + t)*33];
    size_t tb = (size_t)bh*40*128 + t;
    #pragma unroll
    for (int d = 0; d < 32; d++) {
        float cf = RATIO * (scale * ce[d] + FEPS * d_vsum[bh*DH + d]);
        __nv_bfloat16 h, l; split_bf16(cf, h, l);
        d_ctxTh[tb + d*128] = h;
        d_ctxTl[tb + d*128] = l;
    }
    {
        float ks = RATIO * (scale * ce[32] + FEPS * (float)NTOK);
        __nv_bfloat16 h, l; split_bf16(ks, h, l);
        d_ctxTh[tb + 32*128] = h;
        d_ctxTl[tb + 32*128] = l;
    }
    __nv_bfloat16 z = __float2bfloat16_rn(0.0f);
    #pragma unroll
    for (int d = 33; d < 40; d++) {
        d_ctxTh[tb + d*128] = z;
        d_ctxTl[tb + d*128] = z;
    }
}

// ---------------------------------------------------------------------------
// q path via mma.sync: loader is pure copy (prepacked bf16 + diag).
// ---------------------------------------------------------------------------
__global__ __launch_bounds__(256, 2) void q_mms(const float* __restrict__ proj) {
    extern __shared__ char sm[];
    const int PH=0, PL=10240, CTH=20480, CTL=31360,
              EH=42240, EL=77056,          // E: [42240, 111872)
              QH=42240, QL=52480,          // Q aliased inside E
              DG=111872;
    uint32_t sb = smem_u32(sm);
    int bh = blockIdx.y, chunk = blockIdx.x;
    int b = bh >> 3, hd = bh & 7;
    int tid = threadIdx.x, wid = tid >> 5, lane = tid & 31;
    int lrow = tid >> 1, lhalf = tid & 1;
    int wtok = wid * 16;

    // proj -> smem
    {
        const float4* p4 = (const float4*)(proj + lrow*32 + lhalf*16);
        #pragma unroll
        for (int i = 0; i < 4; i++) {
            float4 f = p4[i];
            uint32_t h0, l0, h1, l1;
            split2pack(f.x, f.y, h0, l0);
            split2pack(f.z, f.w, h1, l1);
            int co = lrow*80 + lhalf*32 + i*8;
            *(uint2*)(sm + PH + co) = make_uint2(h0, h1);
            *(uint2*)(sm + PL + co) = make_uint2(l0, l1);
        }
    }
    // ctxT -> smem (40 rows x 128 cols = 16 uint4 groups per row, stride 272B)
    {
        const uint4* gh = (const uint4*)(d_ctxTh + (size_t)bh*40*128);
        const uint4* gl = (const uint4*)(d_ctxTl + (size_t)bh*40*128);
        #pragma unroll
        for (int j = 0; j < 3; j++) {
            int idx = tid + j*256;
            if (idx < 640) {
                int row = idx >> 4, cg = idx & 15;
                *(uint4*)(sm + CTH + row*272 + cg*16) = gh[idx];
                *(uint4*)(sm + CTL + row*272 + cg*16) = gl[idx];
            }
        }
    }

    for (int tile = 0; tile < 4; tile++) {
        int p0 = chunk*512 + tile*128;
        // load q tile + diag (pure copies)
        {
            size_t g = ((size_t)(b*NTOK + p0 + lrow))*CHN + hd*32 + lhalf*16;
            int co = lrow*80 + lhalf*32;
            *(uint4*)(sm + QH + co)      = *(const uint4*)(d_qh + g);
            *(uint4*)(sm + QH + co + 16) = *(const uint4*)(d_qh + g + 8);
            *(uint4*)(sm + QL + co)      = *(const uint4*)(d_ql + g);
            *(uint4*)(sm + QL + co + 16) = *(const uint4*)(d_ql + g + 8);
            if (lhalf == 0)
                ((float*)(sm + DG))[lrow] = d_diagq[(size_t)(b*NTOK + p0 + lrow)*HEADS + hd];
        }
        __syncthreads();

        // MMA1: dash = q . projT
        float acc1[16][4];
        #pragma unroll
        for (int i = 0; i < 16; i++)
            #pragma unroll
            for (int j = 0; j < 4; j++) acc1[i][j] = 0.0f;
        #pragma unroll
        for (int ks = 0; ks < 32; ks += 16) {
            uint32_t ah[4], al[4];
            uint32_t aa = sb + QH + (wtok + (lane & 15))*80 + (ks + ((lane >> 4) << 3))*2;
            ldsm_x4(ah, aa);
            ldsm_x4(al, aa + (QL - QH));
            #pragma unroll
            for (int g = 0; g < 8; g++) {
                uint32_t bhf[4], blf[4];
                uint32_t ba = sb + PH + (g*16 + ((lane >> 4) << 3) + (lane & 7))*80
                                      + (ks + (((lane >> 3) & 1) << 3))*2;
                ldsm_x4(bhf, ba);
                ldsm_x4(blf, ba + (PL - PH));
                #pragma unroll
                for (int h = 0; h < 2; h++) {
                    float* c = acc1[g*2 + h];
                    mma16816(c, ah, &bhf[h*2]);
                    mma16816(c, ah, &blf[h*2]);
                    mma16816(c, al, &bhf[h*2]);
                }
            }
        }
        __syncthreads();   // all warps done reading Q before E overwrites it
        // epilogue 1: per-token max, qp = ratio*(exp(...)+eps)
        {
            int r0 = wtok + (lane >> 2);
            float dg0 = ((float*)(sm + DG))[r0];
            float dg1 = ((float*)(sm + DG))[r0 + 8];
            float mx0 = -INFINITY, mx1 = -INFINITY;
            #pragma unroll
            for (int f = 0; f < 16; f++) {
                mx0 = fmaxf(mx0, fmaxf(acc1[f][0], acc1[f][1]));
                mx1 = fmaxf(mx1, fmaxf(acc1[f][2], acc1[f][3]));
            }
            mx0 = fmaxf(mx0, __shfl_xor_sync(0xffffffffu, mx0, 1));
            mx0 = fmaxf(mx0, __shfl_xor_sync(0xffffffffu, mx0, 2));
            mx1 = fmaxf(mx1, __shfl_xor_sync(0xffffffffu, mx1, 1));
            mx1 = fmaxf(mx1, __shfl_xor_sync(0xffffffffu, mx1, 2));
            mx0 = mx0*DN + dg0;
            mx1 = mx1*DN + dg1;
            int cq = 2*(lane & 3);
            #pragma unroll
            for (int f = 0; f < 16; f++) {
                int c0 = f*8 + cq;
                float e0 = RATIO*(__expf(acc1[f][0]*DN - mx0) + FEPS);
                float e1 = RATIO*(__expf(acc1[f][1]*DN - mx0) + FEPS);
                float e2 = RATIO*(__expf(acc1[f][2]*DN - mx1) + FEPS);
                float e3 = RATIO*(__expf(acc1[f][3]*DN - mx1) + FEPS);
                uint32_t h0, l0, h1, l1;
                split2pack(e0, e1, h0, l0);
                split2pack(e2, e3, h1, l1);
                *(uint32_t*)(sm + EH + r0*272 + c0*2)       = h0;
                *(uint32_t*)(sm + EL + r0*272 + c0*2)       = l0;
                *(uint32_t*)(sm + EH + (r0 + 8)*272 + c0*2) = h1;
                *(uint32_t*)(sm + EL + (r0 + 8)*272 + c0*2) = l1;
            }
        }
        __syncthreads();

        // MMA2: out[16tok][40] = qp . ctxT_aug
        float acc2[5][4];
        #pragma unroll
        for (int i = 0; i < 5; i++)
            #pragma unroll
            for (int j = 0; j < 4; j++) acc2[i][j] = 0.0f;
        #pragma unroll
        for (int ks = 0; ks < 128; ks += 16) {
            uint32_t eh[4], el[4];
            uint32_t aa = sb + EH + (wtok + (lane & 15))*272 + (ks + ((lane >> 4) << 3))*2;
            ldsm_x4(eh, aa);
            ldsm_x4(el, aa + (EL - EH));
            uint32_t b0 = sb + CTH + (((lane >> 4) << 3) + (lane & 7))*272
                                   + (ks + (((lane >> 3) & 1) << 3))*2;
            uint32_t c0h[4], c0l[4], c1h[4], c1l[4], c2h[2], c2l[2];
            ldsm_x4(c0h, b0);
            ldsm_x4(c0l, b0 + (CTL - CTH));
            ldsm_x4(c1h, b0 + 16*272);
            ldsm_x4(c1l, b0 + (CTL - CTH) + 16*272);
            {
                uint32_t b2 = sb + CTH + (32 + (lane & 7))*272
                                       + (ks + (((lane >> 3) & 1) << 3))*2;
                ldsm_x2(c2h, b2);
                ldsm_x2(c2l, b2 + (CTL - CTH));
            }
            const uint32_t* bhf[5] = {&c0h[0], &c0h[2], &c1h[0], &c1h[2], &c2h[0]};
            const uint32_t* blf[5] = {&c0l[0], &c0l[2], &c1l[0], &c1l[2], &c2l[0]};
            #pragma unroll
            for (int nf = 0; nf < 5; nf++) {
                mma16816(acc2[nf], eh, bhf[nf]);
                mma16816(acc2[nf], eh, blf[nf]);
                mma16816(acc2[nf], el, bhf[nf]);
            }
        }
        // epilogue 2: dinv from col 32, write attn bf16 hi/lo
        {
            int r0 = wtok + (lane >> 2), cq = 2*(lane & 3);
            int src = lane & ~3;
            float den0 = __shfl_sync(0xffffffffu, acc2[4][0], src);
            float den1 = __shfl_sync(0xffffffffu, acc2[4][2], src);
            float di0 = 1.0f / den0, di1 = 1.0f / den1;
            size_t g0 = (size_t)(b*NTOK + p0 + r0)*CHN + hd*32;
            size_t g1 = g0 + (size_t)8*CHN;
            #pragma unroll
            for (int nf = 0; nf < 4; nf++) {
                int c0 = nf*8 + cq;
                uint32_t h0, l0, h1, l1;
                split2pack(acc2[nf][0]*di0, acc2[nf][1]*di0, h0, l0);
                split2pack(acc2[nf][2]*di1, acc2[nf][3]*di1, h1, l1);
                *(uint32_t*)(d_ath + g0 + c0) = h0;
                *(uint32_t*)(d_atl + g0 + c0) = l0;
                *(uint32_t*)(d_ath + g1 + c0) = h1;
                *(uint32_t*)(d_atl + g1 + c0) = l1;
            }
        }
        __syncthreads();
    }
}

// ---------------------------------------------------------------------------
// output GEMM via mma.sync (unchanged, passing)
// ---------------------------------------------------------------------------
__global__ __launch_bounds__(256) void out_mms(float* __restrict__ out) {
    __shared__ __align__(16) char smraw[34816];
    __nv_bfloat16 (*Ah)[40] = (__nv_bfloat16(*)[40])(smraw);
    __nv_bfloat16 (*Al)[40] = (__nv_bfloat16(*)[40])(smraw + 10240);
    __nv_bfloat16 (*Bh)[40] = (__nv_bfloat16(*)[40])(smraw + 20480);
    __nv_bfloat16 (*Bl)[40] = (__nv_bfloat16(*)[40])(smraw + 25600);
    float (*Ct)[132] = (float(*)[132])(smraw);

    int m0 = blockIdx.x * 128, n0 = blockIdx.y * 64;
    int tid = threadIdx.x, wid = tid >> 5, lane = tid & 31;
    int wm = (wid & 3) * 32, wn = (wid >> 2) * 32;

    float acc[2][4][4];
    #pragma unroll
    for (int mi = 0; mi < 2; mi++)
        #pragma unroll
        for (int ni = 0; ni < 4; ni++)
            #pragma unroll
            for (int q = 0; q < 4; q++) acc[mi][ni][q] = 0.0f;

    int arow = wm + (lane & 15);
    int acol8 = (lane >> 4) * 8;
    int brow = wn + ((lane >> 4) << 3) + (lane & 7);
    int bcol8 = ((lane >> 3) & 1) * 8;

    for (int ck = 0; ck < 8; ck++) {
        int k0 = ck * 32;
        #pragma unroll
        for (int j = 0; j < 2; j++) {
            int i = tid + j*256, row = i >> 2, cg = i & 3;
            size_t g = (size_t)(m0 + row)*CHN + k0 + cg*8;
            *(uint4*)&Ah[row][cg*8] = *(const uint4*)(d_ath + g);
            *(uint4*)&Al[row][cg*8] = *(const uint4*)(d_atl + g);
        }
        {
            int row = tid >> 2, cg = tid & 3;
            size_t g = (size_t)(n0 + row)*CHN + k0 + cg*8;
            *(uint4*)&Bh[row][cg*8] = *(const uint4*)(d_wch + g);
            *(uint4*)&Bl[row][cg*8] = *(const uint4*)(d_wcl + g);
        }
        __syncthreads();
        #pragma unroll
        for (int ks = 0; ks < 32; ks += 16) {
            uint32_t ah[2][4], al[2][4], bh[2][4], bl[2][4];
            #pragma unroll
            for (int mi = 0; mi < 2; mi++) {
                ldsm_x4(ah[mi], smem_u32(&Ah[arow + mi*16][ks + acol8]));
                ldsm_x4(al[mi], smem_u32(&Al[arow + mi*16][ks + acol8]));
            }
            #pragma unroll
            for (int p = 0; p < 2; p++) {
                ldsm_x4(bh[p], smem_u32(&Bh[brow + p*16][ks + bcol8]));
                ldsm_x4(bl[p], smem_u32(&Bl[brow + p*16][ks + bcol8]));
            }
            #pragma unroll
            for (int mi = 0; mi < 2; mi++)
                #pragma unroll
                for (int ni = 0; ni < 4; ni++) {
                    const uint32_t* bhp = &bh[ni >> 1][(ni & 1)*2];
                    const uint32_t* blp = &bl[ni >> 1][(ni & 1)*2];
                    mma16816(acc[mi][ni], ah[mi], bhp);
                    mma16816(acc[mi][ni], ah[mi], blp);
                    mma16816(acc[mi][ni], al[mi], bhp);
                }
        }
        __syncthreads();
    }

    #pragma unroll
    for (int mi = 0; mi < 2; mi++)
        #pragma unroll
        for (int ni = 0; ni < 4; ni++) {
            int ml = wm + mi*16 + (lane >> 2);
            int nl = wn + ni*8 + 2*(lane & 3);
            Ct[nl][ml]       = acc[mi][ni][0];
            Ct[nl+1][ml]     = acc[mi][ni][1];
            Ct[nl][ml+8]     = acc[mi][ni][2];
            Ct[nl+1][ml+8]   = acc[mi][ni][3];
        }
    __syncthreads();

    int bb = m0 / NTOK, ptok = m0 % NTOK;
    int ch = tid >> 2, tg = tid & 3;
    float bias = d_bcomb[n0 + ch];
    size_t rowb = (size_t)(bb*CHN + n0 + ch) * NTOK + ptok;
    #pragma unroll
    for (int j = 0; j < 8; j++) {
        int tl = tg*32 + j*4;
        float4 v = *(float4*)&Ct[ch][tl];
        *(float4*)&out[rowb + tl] = make_float4(v.x+bias, v.y+bias, v.z+bias, v.w+bias);
    }
}

extern "C" void kernel_launch(void* const* d_in, const int* in_sizes, int n_in,
                              void* d_out, int out_size) {
    const float* x    = (const float*)d_in[0];
    const float* wq   = (const float*)d_in[1];
    const float* wk   = (const float*)d_in[2];
    const float* wv   = (const float*)d_in[3];
    const float* wo   = (const float*)d_in[4];
    const float* bo   = (const float*)d_in[5];
    const float* proj = (const float*)d_in[6];
    const float* wp   = (const float*)d_in[7];
    const float* bp   = (const float*)d_in[8];
    float* out = (float*)d_out;

    cudaFuncSetAttribute(k_mms, cudaFuncAttributeMaxDynamicSharedMemorySize, 111616);
    cudaFuncSetAttribute(q_mms, cudaFuncAttributeMaxDynamicSharedMemorySize, 112640);

    init_k<<<768, 256>>>();
    conv_w<<<dim3(256, 3), 256>>>(wq, wk, wv);
    wcomb_k<<<256, 256>>>(wo, bo, wp, bp);
    xt_k<<<dim3(288, 8, 4), 256>>>(x);
    vsum_k<<<BH, 32>>>(wv);
    qkv_mms<<<dim3(288, 4, 3), 256>>>();
    k_mms<<<dim3(8, BH), 256, 111616>>>(proj);
    k_final<<<BH, 128>>>();
    q_mms<<<dim3(18, BH), 256, 112640>>>(proj);
    out_mms<<<dim3(288, 4), 256>>>(out);
}

// round 12
// speedup vs baseline: 1.0609x; 1.0609x over previous
#include <cuda_runtime.h>
#include <cuda_bf16.h>
#include <math.h>
#include <cstdint>

#define NTOK 9216
#define BATCH 4
#define CHN 256
#define HEADS 8
#define DH 32
#define NB 128
#define BH (BATCH*HEADS)
#define MTOT (BATCH*NTOK)

#define DN 0.4204482076268573f
#define HALF_DN2 0.08838834764831845f
#define RATIO 0.08838834764831845f
#define FEPS 1e-4f

static __device__ float d_q[MTOT*CHN];
static __device__ float d_k[MTOT*CHN];
static __device__ float d_v[MTOT*CHN];
static __device__ float d_ctxe[(size_t)BH*128*33];  // [bh][feat][0..31=ctx, 32=ksum]
static __device__ float d_vsum[BH*DH];
static __device__ float d_xsum[BATCH*CHN];
static __device__ float d_kmax[BH];
static __device__ float d_bcomb[CHN];

static __device__ __nv_bfloat16 d_xth[(size_t)MTOT*CHN];
static __device__ __nv_bfloat16 d_xtl[(size_t)MTOT*CHN];
static __device__ __nv_bfloat16 d_w3h[3*CHN*CHN];
static __device__ __nv_bfloat16 d_w3l[3*CHN*CHN];
static __device__ __nv_bfloat16 d_ath[(size_t)MTOT*CHN];
static __device__ __nv_bfloat16 d_atl[(size_t)MTOT*CHN];
static __device__ __nv_bfloat16 d_wch[CHN*CHN];
static __device__ __nv_bfloat16 d_wcl[CHN*CHN];
static __device__ __nv_bfloat16 d_ctxTh[BH*40*128];  // [bh][row 0..31=ctx_d, 32=ksum, 33..39=0][feat]
static __device__ __nv_bfloat16 d_ctxTl[BH*40*128];

// ---- mma helpers ----
__device__ __forceinline__ uint32_t smem_u32(const void* p) {
    uint32_t a;
    asm("{ .reg .u64 t; cvta.to.shared.u64 t, %1; cvt.u32.u64 %0, t; }" : "=r"(a) : "l"(p));
    return a;
}
__device__ __forceinline__ void ldsm_x4(uint32_t* r, uint32_t addr) {
    asm volatile("ldmatrix.sync.aligned.m8n8.x4.shared.b16 {%0,%1,%2,%3}, [%4];"
        : "=r"(r[0]), "=r"(r[1]), "=r"(r[2]), "=r"(r[3]) : "r"(addr));
}
__device__ __forceinline__ void ldsm_x2(uint32_t* r, uint32_t addr) {
    asm volatile("ldmatrix.sync.aligned.m8n8.x2.shared.b16 {%0,%1}, [%2];"
        : "=r"(r[0]), "=r"(r[1]) : "r"(addr));
}
__device__ __forceinline__ void ldsm_x4_t(uint32_t* r, uint32_t addr) {
    asm volatile("ldmatrix.sync.aligned.m8n8.x4.trans.shared.b16 {%0,%1,%2,%3}, [%4];"
        : "=r"(r[0]), "=r"(r[1]), "=r"(r[2]), "=r"(r[3]) : "r"(addr));
}
__device__ __forceinline__ void ldsm_x2_t(uint32_t* r, uint32_t addr) {
    asm volatile("ldmatrix.sync.aligned.m8n8.x2.trans.shared.b16 {%0,%1}, [%2];"
        : "=r"(r[0]), "=r"(r[1]) : "r"(addr));
}
__device__ __forceinline__ void mma16816(float* c, const uint32_t* a, const uint32_t* b) {
    asm volatile("mma.sync.aligned.m16n8k16.row.col.f32.bf16.bf16.f32 "
        "{%0,%1,%2,%3}, {%4,%5,%6,%7}, {%8,%9}, {%0,%1,%2,%3};"
        : "+f"(c[0]), "+f"(c[1]), "+f"(c[2]), "+f"(c[3])
        : "r"(a[0]), "r"(a[1]), "r"(a[2]), "r"(a[3]), "r"(b[0]), "r"(b[1]));
}
__device__ __forceinline__ void atomicMaxFloat(float* addr, float val) {
    int* ai = (int*)addr;
    int old = __float_as_int(*addr);
    while (__int_as_float(old) < val) {
        int assumed = old;
        old = atomicCAS(ai, assumed, __float_as_int(val));
        if (old == assumed) break;
    }
}
__device__ __forceinline__ void split_bf16(float v, __nv_bfloat16& h, __nv_bfloat16& l) {
    h = __float2bfloat16_rn(v);
    l = __float2bfloat16_rn(v - __bfloat162float(h));
}
__device__ __forceinline__ void split2pack(float a, float b, uint32_t& hi, uint32_t& lo) {
    __nv_bfloat16 ha = __float2bfloat16_rn(a);
    __nv_bfloat16 hb = __float2bfloat16_rn(b);
    __nv_bfloat16 la = __float2bfloat16_rn(a - __bfloat162float(ha));
    __nv_bfloat16 lb = __float2bfloat16_rn(b - __bfloat162float(hb));
    hi = (uint32_t)(*(unsigned short*)&ha) | ((uint32_t)(*(unsigned short*)&hb) << 16);
    lo = (uint32_t)(*(unsigned short*)&la) | ((uint32_t)(*(unsigned short*)&lb) << 16);
}

// ---------------------------------------------------------------------------
__global__ void init_k() {
    int i = blockIdx.x * 256 + threadIdx.x;
    if (i < BH*128*33) d_ctxe[i] = 0.0f;
    if (i < BATCH*CHN) d_xsum[i] = 0.0f;
    if (i < BH)        d_kmax[i] = -INFINITY;
}

__global__ __launch_bounds__(256) void conv_w(const float* __restrict__ wq,
                                              const float* __restrict__ wk,
                                              const float* __restrict__ wv) {
    int z = blockIdx.y, o = blockIdx.x, c = threadIdx.x;
    const float* W = (z == 0) ? wq : ((z == 1) ? wk : wv);
    float v = W[o*CHN + c];
    __nv_bfloat16 h, l; split_bf16(v, h, l);
    d_w3h[(z*CHN + o)*CHN + c] = h;
    d_w3l[(z*CHN + o)*CHN + c] = l;
}

__global__ __launch_bounds__(256) void wcomb_k(const float* __restrict__ wo,
                                               const float* __restrict__ bo,
                                               const float* __restrict__ wp,
                                               const float* __restrict__ bp) {
    int o = blockIdx.x, c = threadIdx.x;
    float acc = 0.0f;
    for (int j = 0; j < CHN; j++) acc += wp[o*CHN + j] * wo[j*CHN + c];
    __nv_bfloat16 h, l; split_bf16(acc, h, l);
    d_wch[o*CHN + c] = h;
    d_wcl[o*CHN + c] = l;
    if (c == 0) {
        float bcc = 0.0f;
        for (int j = 0; j < CHN; j++) bcc += wp[o*CHN + j] * bo[j];
        d_bcomb[o] = bcc + bp[o];
    }
}

// ---------------------------------------------------------------------------
// transpose x -> bf16 hi/lo + accumulate xsum[b][c]
// ---------------------------------------------------------------------------
__global__ __launch_bounds__(256) void xt_k(const float* __restrict__ x) {
    __shared__ float ts[32][33];
    int b = blockIdx.z, c0 = blockIdx.y * 32, p0 = blockIdx.x * 32;
    int tid = threadIdx.x;
    int tx = tid & 31, ty = tid >> 5;
    #pragma unroll
    for (int i = 0; i < 4; i++) {
        int c = c0 + ty + i*8;
        ts[ty + i*8][tx] = x[((size_t)(b*CHN + c))*NTOK + p0 + tx];
    }
    __syncthreads();
    {
        int cl = tid >> 3, j0 = (tid & 7)*4;
        float s = ts[cl][j0] + ts[cl][j0+1] + ts[cl][j0+2] + ts[cl][j0+3];
        s += __shfl_xor_sync(0xffffffffu, s, 1);
        s += __shfl_xor_sync(0xffffffffu, s, 2);
        s += __shfl_xor_sync(0xffffffffu, s, 4);
        if ((tid & 7) == 0) atomicAdd(&d_xsum[b*CHN + c0 + cl], s);
    }
    #pragma unroll
    for (int i = 0; i < 4; i++) {
        int p = p0 + ty + i*8;
        float v = ts[tx][ty + i*8];
        size_t gi = (size_t)(b*NTOK + p)*CHN + c0 + tx;
        __nv_bfloat16 h, l; split_bf16(v, h, l);
        d_xth[gi] = h;
        d_xtl[gi] = l;
    }
}

__global__ __launch_bounds__(32) void vsum_k(const float* __restrict__ wv) {
    int bh = blockIdx.x, d = threadIdx.x;
    int b = bh >> 3, hd = bh & 7;
    const float* xs = &d_xsum[b*CHN];
    const float* wr = &wv[(hd*32 + d)*CHN];
    float s = 0.0f;
    for (int c = 0; c < CHN; c++) s += xs[c]*wr[c];
    d_vsum[bh*32 + d] = s;
}

// ---------------------------------------------------------------------------
// QKV GEMM via mma.sync: 128x128 block tile (halves A-tile traffic).
// 8 warps, each 32(m) x 64(n). B frags loaded per-16-row group in-loop.
// ---------------------------------------------------------------------------
__global__ __launch_bounds__(256) void qkv_mms() {
    __shared__ __align__(16) __nv_bfloat16 Ah[128][40];
    __shared__ __align__(16) __nv_bfloat16 Al[128][40];
    __shared__ __align__(16) __nv_bfloat16 Bh[128][40];
    __shared__ __align__(16) __nv_bfloat16 Bl[128][40];

    int z = blockIdx.z;
    const __nv_bfloat16* WH = d_w3h + (size_t)z*CHN*CHN;
    const __nv_bfloat16* WL = d_w3l + (size_t)z*CHN*CHN;
    float* C = (z == 0) ? d_q : ((z == 1) ? d_k : d_v);
    int m0 = blockIdx.x * 128, n0 = blockIdx.y * 128;
    int tid = threadIdx.x, wid = tid >> 5, lane = tid & 31;
    int wm = (wid & 3) * 32, wn = (wid >> 2) * 64;

    float acc[2][8][4];
    #pragma unroll
    for (int mi = 0; mi < 2; mi++)
        #pragma unroll
        for (int ni = 0; ni < 8; ni++)
            #pragma unroll
            for (int q = 0; q < 4; q++) acc[mi][ni][q] = 0.0f;

    int arow = wm + (lane & 15);
    int acol8 = (lane >> 4) * 8;
    int brow = wn + ((lane >> 4) << 3) + (lane & 7);
    int bcol8 = ((lane >> 3) & 1) * 8;

    for (int ck = 0; ck < 8; ck++) {
        int k0 = ck * 32;
        #pragma unroll
        for (int j = 0; j < 2; j++) {
            int i = tid + j*256, row = i >> 2, cg = i & 3;
            size_t g = (size_t)(m0 + row)*CHN + k0 + cg*8;
            *(uint4*)&Ah[row][cg*8] = *(const uint4*)(d_xth + g);
            *(uint4*)&Al[row][cg*8] = *(const uint4*)(d_xtl + g);
        }
        #pragma unroll
        for (int j = 0; j < 2; j++) {
            int i = tid + j*256, row = i >> 2, cg = i & 3;
            size_t g = (size_t)(n0 + row)*CHN + k0 + cg*8;
            *(uint4*)&Bh[row][cg*8] = *(const uint4*)(WH + g);
            *(uint4*)&Bl[row][cg*8] = *(const uint4*)(WL + g);
        }
        __syncthreads();
        #pragma unroll
        for (int ks = 0; ks < 32; ks += 16) {
            uint32_t ah[2][4], al[2][4];
            #pragma unroll
            for (int mi = 0; mi < 2; mi++) {
                ldsm_x4(ah[mi], smem_u32(&Ah[arow + mi*16][ks + acol8]));
                ldsm_x4(al[mi], smem_u32(&Al[arow + mi*16][ks + acol8]));
            }
            #pragma unroll
            for (int p = 0; p < 4; p++) {
                uint32_t bhp[4], blp[4];
                ldsm_x4(bhp, smem_u32(&Bh[brow + p*16][ks + bcol8]));
                ldsm_x4(blp, smem_u32(&Bl[brow + p*16][ks + bcol8]));
                #pragma unroll
                for (int mi = 0; mi < 2; mi++)
                    #pragma unroll
                    for (int h = 0; h < 2; h++) {
                        float* c = acc[mi][p*2 + h];
                        mma16816(c, ah[mi], &bhp[h*2]);
                        mma16816(c, ah[mi], &blp[h*2]);
                        mma16816(c, al[mi], &bhp[h*2]);
                    }
            }
        }
        __syncthreads();
    }
    #pragma unroll
    for (int mi = 0; mi < 2; mi++)
        #pragma unroll
        for (int ni = 0; ni < 8; ni++) {
            int m = m0 + wm + mi*16 + (lane >> 2);
            int n = n0 + wn + ni*8 + 2*(lane & 3);
            *(float2*)&C[(size_t)m*CHN + n]     = make_float2(acc[mi][ni][0], acc[mi][ni][1]);
            *(float2*)&C[(size_t)(m+8)*CHN + n] = make_float2(acc[mi][ni][2], acc[mi][ni][3]);
        }
}

// ---------------------------------------------------------------------------
// k path via mma.sync. smem aliased: K tile lives inside E region.
// ---------------------------------------------------------------------------
__global__ __launch_bounds__(256, 2) void k_mms(const float* __restrict__ proj) {
    extern __shared__ char sm[];
    const int PH=0, PL=10240, VH=20480, VL=30720,
              EH=40960, EL=75776,           // E: [40960, 110592)
              KH=40960, KL=51200,           // K aliased inside E
              DG=110592, RED=111104;
    uint32_t sb = smem_u32(sm);
    int bh = blockIdx.y, chunk = blockIdx.x;
    int b = bh >> 3, hd = bh & 7;
    int tid = threadIdx.x, wid = tid >> 5, lane = tid & 31;
    int lrow = tid >> 1, lhalf = tid & 1;
    int wtok = wid * 16, wf = wid * 16;

    {
        const float4* p4 = (const float4*)(proj + lrow*32 + lhalf*16);
        #pragma unroll
        for (int i = 0; i < 4; i++) {
            float4 f = p4[i];
            uint32_t h0, l0, h1, l1;
            split2pack(f.x, f.y, h0, l0);
            split2pack(f.z, f.w, h1, l1);
            int co = lrow*80 + lhalf*32 + i*8;
            *(uint2*)(sm + PH + co) = make_uint2(h0, h1);
            *(uint2*)(sm + PL + co) = make_uint2(l0, l1);
        }
    }

    float lmax = -INFINITY;
    float acc2[5][4];
    #pragma unroll
    for (int i = 0; i < 5; i++)
        #pragma unroll
        for (int j = 0; j < 4; j++) acc2[i][j] = 0.0f;

    for (int tile = 0; tile < 9; tile++) {
        int p0 = chunk*1152 + tile*128;
        {
            size_t g = ((size_t)(b*NTOK + p0 + lrow))*CHN + hd*32 + lhalf*16;
            const float4* k4 = (const float4*)(d_k + g);
            const float4* v4 = (const float4*)(d_v + g);
            float sq = 0.0f;
            #pragma unroll
            for (int i = 0; i < 4; i++) {
                float4 kf = k4[i];
                sq += kf.x*kf.x + kf.y*kf.y + kf.z*kf.z + kf.w*kf.w;
                uint32_t h0, l0, h1, l1;
                split2pack(kf.x, kf.y, h0, l0); split2pack(kf.z, kf.w, h1, l1);
                int co = lrow*80 + lhalf*32 + i*8;
                *(uint2*)(sm + KH + co) = make_uint2(h0, h1);
                *(uint2*)(sm + KL + co) = make_uint2(l0, l1);
                float4 vf = v4[i];
                split2pack(vf.x, vf.y, h0, l0); split2pack(vf.z, vf.w, h1, l1);
                *(uint2*)(sm + VH + co) = make_uint2(h0, h1);
                *(uint2*)(sm + VL + co) = make_uint2(l0, l1);
            }
            sq += __shfl_xor_sync(0xffffffffu, sq, 1);
            if (lhalf == 0) {
                ((float*)(sm + DG))[lrow] = sq * HALF_DN2;
            } else {
                *(uint4*)(sm + VH + lrow*80 + 64) = make_uint4(0x00003F80u, 0u, 0u, 0u);
                *(uint4*)(sm + VL + lrow*80 + 64) = make_uint4(0u, 0u, 0u, 0u);
            }
        }
        __syncthreads();

        float acc1[16][4];
        #pragma unroll
        for (int i = 0; i < 16; i++)
            #pragma unroll
            for (int j = 0; j < 4; j++) acc1[i][j] = 0.0f;
        #pragma unroll
        for (int ks = 0; ks < 32; ks += 16) {
            uint32_t ah[4], al[4];
            uint32_t aa = sb + KH + (wtok + (lane & 15))*80 + (ks + ((lane >> 4) << 3))*2;
            ldsm_x4(ah, aa);
            ldsm_x4(al, aa + (KL - KH));
            #pragma unroll
            for (int g = 0; g < 8; g++) {
                uint32_t bhf[4], blf[4];
                uint32_t ba = sb + PH + (g*16 + ((lane >> 4) << 3) + (lane & 7))*80
                                      + (ks + (((lane >> 3) & 1) << 3))*2;
                ldsm_x4(bhf, ba);
                ldsm_x4(blf, ba + (PL - PH));
                #pragma unroll
                for (int h = 0; h < 2; h++) {
                    float* c = acc1[g*2 + h];
                    mma16816(c, ah, &bhf[h*2]);
                    mma16816(c, ah, &blf[h*2]);
                    mma16816(c, al, &bhf[h*2]);
                }
            }
        }
        __syncthreads();   // all warps done reading K before E overwrites it
        {
            int r0 = wtok + (lane >> 2), cq = 2*(lane & 3);
            float dg0 = ((float*)(sm + DG))[r0];
            float dg1 = ((float*)(sm + DG))[r0 + 8];
            #pragma unroll
            for (int f = 0; f < 16; f++) {
                int c0 = f*8 + cq;
                float v0 = acc1[f][0]*DN, v1 = acc1[f][1]*DN;
                float v2 = acc1[f][2]*DN, v3 = acc1[f][3]*DN;
                lmax = fmaxf(lmax, fmaxf(fmaxf(v0, v1), fmaxf(v2, v3)));
                uint32_t h0, l0, h1, l1;
                split2pack(__expf(v0 - dg0), __expf(v1 - dg0), h0, l0);
                split2pack(__expf(v2 - dg1), __expf(v3 - dg1), h1, l1);
                *(uint32_t*)(sm + EH + r0*272 + c0*2)       = h0;
                *(uint32_t*)(sm + EL + r0*272 + c0*2)       = l0;
                *(uint32_t*)(sm + EH + (r0 + 8)*272 + c0*2) = h1;
                *(uint32_t*)(sm + EL + (r0 + 8)*272 + c0*2) = l1;
            }
        }
        __syncthreads();

        #pragma unroll
        for (int kk = 0; kk < 8; kk++) {
            int tok0 = kk*16;
            uint32_t eh[4], el[4];
            uint32_t aa = sb + EH + (tok0 + ((lane >> 4) << 3) + (lane & 7))*272
                                  + (wf + (((lane >> 3) & 1) << 3))*2;
            ldsm_x4_t(eh, aa);
            ldsm_x4_t(el, aa + (EL - EH));
            uint32_t vrowb = sb + VH + (tok0 + (((lane >> 3) & 1) << 3) + (lane & 7))*80;
            uint32_t doff = ((lane >> 4) << 3)*2;
            uint32_t vh0[4], vl0[4], vh1[4], vl1[4], v2h[2], v2l[2];
            ldsm_x4_t(vh0, vrowb + doff);
            ldsm_x4_t(vl0, vrowb + (VL - VH) + doff);
            ldsm_x4_t(vh1, vrowb + 32 + doff);
            ldsm_x4_t(vl1, vrowb + (VL - VH) + 32 + doff);
            ldsm_x2_t(v2h, vrowb + 64);
            ldsm_x2_t(v2l, vrowb + (VL - VH) + 64);
            const uint32_t* bhf[5] = {&vh0[0], &vh0[2], &vh1[0], &vh1[2], &v2h[0]};
            const uint32_t* blf[5] = {&vl0[0], &vl0[2], &vl1[0], &vl1[2], &v2l[0]};
            #pragma unroll
            for (int nf = 0; nf < 5; nf++) {
                mma16816(acc2[nf], eh, bhf[nf]);
                mma16816(acc2[nf], eh, blf[nf]);
                mma16816(acc2[nf], el, bhf[nf]);
            }
        }
        __syncthreads();
    }

    #pragma unroll
    for (int off = 16; off > 0; off >>= 1)
        lmax = fmaxf(lmax, __shfl_xor_sync(0xffffffffu, lmax, off));
    if (lane == 0) ((float*)(sm + RED))[wid] = lmax;
    __syncthreads();
    if (tid == 0) {
        float m = ((float*)(sm + RED))[0];
        #pragma unroll
        for (int i = 1; i < 8; i++) m = fmaxf(m, ((float*)(sm + RED))[i]);
        atomicMaxFloat(&d_kmax[bh], m);
    }
    {
        int r0 = wf + (lane >> 2), cq = 2*(lane & 3);
        #pragma unroll
        for (int nf = 0; nf < 4; nf++) {
            int c0 = nf*8 + cq;
            float* pa = &d_ctxe[((size_t)bh*128 + r0)*33 + c0];
            float* pb = &d_ctxe[((size_t)bh*128 + r0 + 8)*33 + c0];
            atomicAdd(pa,     acc2[nf][0]); atomicAdd(pa + 1, acc2[nf][1]);
            atomicAdd(pb,     acc2[nf][2]); atomicAdd(pb + 1, acc2[nf][3]);
        }
        if ((lane & 3) == 0) {
            atomicAdd(&d_ctxe[((size_t)bh*128 + r0)*33 + 32],     acc2[4][0]);
            atomicAdd(&d_ctxe[((size_t)bh*128 + r0 + 8)*33 + 32], acc2[4][2]);
        }
    }
}

// ---------------------------------------------------------------------------
// finalize -> transposed augmented ctxT bf16 hi/lo
// ---------------------------------------------------------------------------
__global__ __launch_bounds__(128) void k_final() {
    int bh = blockIdx.x, t = threadIdx.x;  // t = feat
    float scale = __expf(-d_kmax[bh]);
    const float* ce = &d_ctxe[((size_t)bh*128 + t)*33];
    size_t tb = (size_t)bh*40*128 + t;
    #pragma unroll
    for (int d = 0; d < 32; d++) {
        float cf = RATIO * (scale * ce[d] + FEPS * d_vsum[bh*DH + d]);
        __nv_bfloat16 h, l; split_bf16(cf, h, l);
        d_ctxTh[tb + d*128] = h;
        d_ctxTl[tb + d*128] = l;
    }
    {
        float ks = RATIO * (scale * ce[32] + FEPS * (float)NTOK);
        __nv_bfloat16 h, l; split_bf16(ks, h, l);
        d_ctxTh[tb + 32*128] = h;
        d_ctxTl[tb + 32*128] = l;
    }
    __nv_bfloat16 z = __float2bfloat16_rn(0.0f);
    #pragma unroll
    for (int d = 33; d < 40; d++) {
        d_ctxTh[tb + d*128] = z;
        d_ctxTl[tb + d*128] = z;
    }
}

// ---------------------------------------------------------------------------
// q path via mma.sync. smem aliased: Q tile inside E region.
// ---------------------------------------------------------------------------
__global__ __launch_bounds__(256, 2) void q_mms(const float* __restrict__ proj) {
    extern __shared__ char sm[];
    const int PH=0, PL=10240, CTH=20480, CTL=31360,
              EH=42240, EL=77056,          // E: [42240, 111872)
              QH=42240, QL=52480,          // Q aliased inside E
              DG=111872;
    uint32_t sb = smem_u32(sm);
    int bh = blockIdx.y, chunk = blockIdx.x;
    int b = bh >> 3, hd = bh & 7;
    int tid = threadIdx.x, wid = tid >> 5, lane = tid & 31;
    int lrow = tid >> 1, lhalf = tid & 1;
    int wtok = wid * 16;

    // proj -> smem
    {
        const float4* p4 = (const float4*)(proj + lrow*32 + lhalf*16);
        #pragma unroll
        for (int i = 0; i < 4; i++) {
            float4 f = p4[i];
            uint32_t h0, l0, h1, l1;
            split2pack(f.x, f.y, h0, l0);
            split2pack(f.z, f.w, h1, l1);
            int co = lrow*80 + lhalf*32 + i*8;
            *(uint2*)(sm + PH + co) = make_uint2(h0, h1);
            *(uint2*)(sm + PL + co) = make_uint2(l0, l1);
        }
    }
    // ctxT -> smem (40 rows x 128 cols = 16 uint4 groups per row, stride 272B)
    {
        const uint4* gh = (const uint4*)(d_ctxTh + (size_t)bh*40*128);
        const uint4* gl = (const uint4*)(d_ctxTl + (size_t)bh*40*128);
        #pragma unroll
        for (int j = 0; j < 3; j++) {
            int idx = tid + j*256;
            if (idx < 640) {
                int row = idx >> 4, cg = idx & 15;
                *(uint4*)(sm + CTH + row*272 + cg*16) = gh[idx];
                *(uint4*)(sm + CTL + row*272 + cg*16) = gl[idx];
            }
        }
    }

    for (int tile = 0; tile < 4; tile++) {
        int p0 = chunk*512 + tile*128;
        // load q tile + diag
        {
            size_t g = ((size_t)(b*NTOK + p0 + lrow))*CHN + hd*32 + lhalf*16;
            const float4* q4 = (const float4*)(d_q + g);
            float sq = 0.0f;
            #pragma unroll
            for (int i = 0; i < 4; i++) {
                float4 qf = q4[i];
                sq += qf.x*qf.x + qf.y*qf.y + qf.z*qf.z + qf.w*qf.w;
                uint32_t h0, l0, h1, l1;
                split2pack(qf.x, qf.y, h0, l0); split2pack(qf.z, qf.w, h1, l1);
                int co = lrow*80 + lhalf*32 + i*8;
                *(uint2*)(sm + QH + co) = make_uint2(h0, h1);
                *(uint2*)(sm + QL + co) = make_uint2(l0, l1);
            }
            sq += __shfl_xor_sync(0xffffffffu, sq, 1);
            if (lhalf == 0) ((float*)(sm + DG))[lrow] = sq * HALF_DN2;
        }
        __syncthreads();

        // MMA1: dash = q . projT
        float acc1[16][4];
        #pragma unroll
        for (int i = 0; i < 16; i++)
            #pragma unroll
            for (int j = 0; j < 4; j++) acc1[i][j] = 0.0f;
        #pragma unroll
        for (int ks = 0; ks < 32; ks += 16) {
            uint32_t ah[4], al[4];
            uint32_t aa = sb + QH + (wtok + (lane & 15))*80 + (ks + ((lane >> 4) << 3))*2;
            ldsm_x4(ah, aa);
            ldsm_x4(al, aa + (QL - QH));
            #pragma unroll
            for (int g = 0; g < 8; g++) {
                uint32_t bhf[4], blf[4];
                uint32_t ba = sb + PH + (g*16 + ((lane >> 4) << 3) + (lane & 7))*80
                                      + (ks + (((lane >> 3) & 1) << 3))*2;
                ldsm_x4(bhf, ba);
                ldsm_x4(blf, ba + (PL - PH));
                #pragma unroll
                for (int h = 0; h < 2; h++) {
                    float* c = acc1[g*2 + h];
                    mma16816(c, ah, &bhf[h*2]);
                    mma16816(c, ah, &blf[h*2]);
                    mma16816(c, al, &bhf[h*2]);
                }
            }
        }
        __syncthreads();   // all warps done reading Q before E overwrites it
        // epilogue 1: per-token max, qp = ratio*(exp(...)+eps)
        {
            int r0 = wtok + (lane >> 2);
            float dg0 = ((float*)(sm + DG))[r0];
            float dg1 = ((float*)(sm + DG))[r0 + 8];
            float mx0 = -INFINITY, mx1 = -INFINITY;
            #pragma unroll
            for (int f = 0; f < 16; f++) {
                mx0 = fmaxf(mx0, fmaxf(acc1[f][0], acc1[f][1]));
                mx1 = fmaxf(mx1, fmaxf(acc1[f][2], acc1[f][3]));
            }
            mx0 = fmaxf(mx0, __shfl_xor_sync(0xffffffffu, mx0, 1));
            mx0 = fmaxf(mx0, __shfl_xor_sync(0xffffffffu, mx0, 2));
            mx1 = fmaxf(mx1, __shfl_xor_sync(0xffffffffu, mx1, 1));
            mx1 = fmaxf(mx1, __shfl_xor_sync(0xffffffffu, mx1, 2));
            mx0 = mx0*DN + dg0;
            mx1 = mx1*DN + dg1;
            int cq = 2*(lane & 3);
            #pragma unroll
            for (int f = 0; f < 16; f++) {
                int c0 = f*8 + cq;
                float e0 = RATIO*(__expf(acc1[f][0]*DN - mx0) + FEPS);
                float e1 = RATIO*(__expf(acc1[f][1]*DN - mx0) + FEPS);
                float e2 = RATIO*(__expf(acc1[f][2]*DN - mx1) + FEPS);
                float e3 = RATIO*(__expf(acc1[f][3]*DN - mx1) + FEPS);
                uint32_t h0, l0, h1, l1;
                split2pack(e0, e1, h0, l0);
                split2pack(e2, e3, h1, l1);
                *(uint32_t*)(sm + EH + r0*272 + c0*2)       = h0;
                *(uint32_t*)(sm + EL + r0*272 + c0*2)       = l0;
                *(uint32_t*)(sm + EH + (r0 + 8)*272 + c0*2) = h1;
                *(uint32_t*)(sm + EL + (r0 + 8)*272 + c0*2) = l1;
            }
        }
        __syncthreads();

        // MMA2: out[16tok][40] = qp . ctxT_aug
        float acc2[5][4];
        #pragma unroll
        for (int i = 0; i < 5; i++)
            #pragma unroll
            for (int j = 0; j < 4; j++) acc2[i][j] = 0.0f;
        #pragma unroll
        for (int ks = 0; ks < 128; ks += 16) {
            uint32_t eh[4], el[4];
            uint32_t aa = sb + EH + (wtok + (lane & 15))*272 + (ks + ((lane >> 4) << 3))*2;
            ldsm_x4(eh, aa);
            ldsm_x4(el, aa + (EL - EH));
            uint32_t b0 = sb + CTH + (((lane >> 4) << 3) + (lane & 7))*272
                                   + (ks + (((lane >> 3) & 1) << 3))*2;
            uint32_t c0h[4], c0l[4], c1h[4], c1l[4], c2h[2], c2l[2];
            ldsm_x4(c0h, b0);
            ldsm_x4(c0l, b0 + (CTL - CTH));
            ldsm_x4(c1h, b0 + 16*272);
            ldsm_x4(c1l, b0 + (CTL - CTH) + 16*272);
            {
                uint32_t b2 = sb + CTH + (32 + (lane & 7))*272
                                       + (ks + (((lane >> 3) & 1) << 3))*2;
                ldsm_x2(c2h, b2);
                ldsm_x2(c2l, b2 + (CTL - CTH));
            }
            const uint32_t* bhf[5] = {&c0h[0], &c0h[2], &c1h[0], &c1h[2], &c2h[0]};
            const uint32_t* blf[5] = {&c0l[0], &c0l[2], &c1l[0], &c1l[2], &c2l[0]};
            #pragma unroll
            for (int nf = 0; nf < 5; nf++) {
                mma16816(acc2[nf], eh, bhf[nf]);
                mma16816(acc2[nf], eh, blf[nf]);
                mma16816(acc2[nf], el, bhf[nf]);
            }
        }
        // epilogue 2: dinv from col 32, write attn bf16 hi/lo
        {
            int r0 = wtok + (lane >> 2), cq = 2*(lane & 3);
            int src = lane & ~3;
            float den0 = __shfl_sync(0xffffffffu, acc2[4][0], src);
            float den1 = __shfl_sync(0xffffffffu, acc2[4][2], src);
            float di0 = 1.0f / den0, di1 = 1.0f / den1;
            size_t g0 = (size_t)(b*NTOK + p0 + r0)*CHN + hd*32;
            size_t g1 = g0 + (size_t)8*CHN;
            #pragma unroll
            for (int nf = 0; nf < 4; nf++) {
                int c0 = nf*8 + cq;
                uint32_t h0, l0, h1, l1;
                split2pack(acc2[nf][0]*di0, acc2[nf][1]*di0, h0, l0);
                split2pack(acc2[nf][2]*di1, acc2[nf][3]*di1, h1, l1);
                *(uint32_t*)(d_ath + g0 + c0) = h0;
                *(uint32_t*)(d_atl + g0 + c0) = l0;
                *(uint32_t*)(d_ath + g1 + c0) = h1;
                *(uint32_t*)(d_atl + g1 + c0) = l1;
            }
        }
        __syncthreads();
    }
}

// ---------------------------------------------------------------------------
// output GEMM via mma.sync (unchanged, passing)
// ---------------------------------------------------------------------------
__global__ __launch_bounds__(256) void out_mms(float* __restrict__ out) {
    __shared__ __align__(16) char smraw[34816];
    __nv_bfloat16 (*Ah)[40] = (__nv_bfloat16(*)[40])(smraw);
    __nv_bfloat16 (*Al)[40] = (__nv_bfloat16(*)[40])(smraw + 10240);
    __nv_bfloat16 (*Bh)[40] = (__nv_bfloat16(*)[40])(smraw + 20480);
    __nv_bfloat16 (*Bl)[40] = (__nv_bfloat16(*)[40])(smraw + 25600);
    float (*Ct)[132] = (float(*)[132])(smraw);

    int m0 = blockIdx.x * 128, n0 = blockIdx.y * 64;
    int tid = threadIdx.x, wid = tid >> 5, lane = tid & 31;
    int wm = (wid & 3) * 32, wn = (wid >> 2) * 32;

    float acc[2][4][4];
    #pragma unroll
    for (int mi = 0; mi < 2; mi++)
        #pragma unroll
        for (int ni = 0; ni < 4; ni++)
            #pragma unroll
            for (int q = 0; q < 4; q++) acc[mi][ni][q] = 0.0f;

    int arow = wm + (lane & 15);
    int acol8 = (lane >> 4) * 8;
    int brow = wn + ((lane >> 4) << 3) + (lane & 7);
    int bcol8 = ((lane >> 3) & 1) * 8;

    for (int ck = 0; ck < 8; ck++) {
        int k0 = ck * 32;
        #pragma unroll
        for (int j = 0; j < 2; j++) {
            int i = tid + j*256, row = i >> 2, cg = i & 3;
            size_t g = (size_t)(m0 + row)*CHN + k0 + cg*8;
            *(uint4*)&Ah[row][cg*8] = *(const uint4*)(d_ath + g);
            *(uint4*)&Al[row][cg*8] = *(const uint4*)(d_atl + g);
        }
        {
            int row = tid >> 2, cg = tid & 3;
            size_t g = (size_t)(n0 + row)*CHN + k0 + cg*8;
            *(uint4*)&Bh[row][cg*8] = *(const uint4*)(d_wch + g);
            *(uint4*)&Bl[row][cg*8] = *(const uint4*)(d_wcl + g);
        }
        __syncthreads();
        #pragma unroll
        for (int ks = 0; ks < 32; ks += 16) {
            uint32_t ah[2][4], al[2][4], bh[2][4], bl[2][4];
            #pragma unroll
            for (int mi = 0; mi < 2; mi++) {
                ldsm_x4(ah[mi], smem_u32(&Ah[arow + mi*16][ks + acol8]));
                ldsm_x4(al[mi], smem_u32(&Al[arow + mi*16][ks + acol8]));
            }
            #pragma unroll
            for (int p = 0; p < 2; p++) {
                ldsm_x4(bh[p], smem_u32(&Bh[brow + p*16][ks + bcol8]));
                ldsm_x4(bl[p], smem_u32(&Bl[brow + p*16][ks + bcol8]));
            }
            #pragma unroll
            for (int mi = 0; mi < 2; mi++)
                #pragma unroll
                for (int ni = 0; ni < 4; ni++) {
                    const uint32_t* bhp = &bh[ni >> 1][(ni & 1)*2];
                    const uint32_t* blp = &bl[ni >> 1][(ni & 1)*2];
                    mma16816(acc[mi][ni], ah[mi], bhp);
                    mma16816(acc[mi][ni], ah[mi], blp);
                    mma16816(acc[mi][ni], al[mi], bhp);
                }
        }
        __syncthreads();
    }

    #pragma unroll
    for (int mi = 0; mi < 2; mi++)
        #pragma unroll
        for (int ni = 0; ni < 4; ni++) {
            int ml = wm + mi*16 + (lane >> 2);
            int nl = wn + ni*8 + 2*(lane & 3);
            Ct[nl][ml]       = acc[mi][ni][0];
            Ct[nl+1][ml]     = acc[mi][ni][1];
            Ct[nl][ml+8]     = acc[mi][ni][2];
            Ct[nl+1][ml+8]   = acc[mi][ni][3];
        }
    __syncthreads();

    int bb = m0 / NTOK, ptok = m0 % NTOK;
    int ch = tid >> 2, tg = tid & 3;
    float bias = d_bcomb[n0 + ch];
    size_t rowb = (size_t)(bb*CHN + n0 + ch) * NTOK + ptok;
    #pragma unroll
    for (int j = 0; j < 8; j++) {
        int tl = tg*32 + j*4;
        float4 v = *(float4*)&Ct[ch][tl];
        *(float4*)&out[rowb + tl] = make_float4(v.x+bias, v.y+bias, v.z+bias, v.w+bias);
    }
}

extern "C" void kernel_launch(void* const* d_in, const int* in_sizes, int n_in,
                              void* d_out, int out_size) {
    const float* x    = (const float*)d_in[0];
    const float* wq   = (const float*)d_in[1];
    const float* wk   = (const float*)d_in[2];
    const float* wv   = (const float*)d_in[3];
    const float* wo   = (const float*)d_in[4];
    const float* bo   = (const float*)d_in[5];
    const float* proj = (const float*)d_in[6];
    const float* wp   = (const float*)d_in[7];
    const float* bp   = (const float*)d_in[8];
    float* out = (float*)d_out;

    cudaFuncSetAttribute(k_mms, cudaFuncAttributeMaxDynamicSharedMemorySize, 111616);
    cudaFuncSetAttribute(q_mms, cudaFuncAttributeMaxDynamicSharedMemorySize, 112640);

    init_k<<<768, 256>>>();
    conv_w<<<dim3(256, 3), 256>>>(wq, wk, wv);
    wcomb_k<<<256, 256>>>(wo, bo, wp, bp);
    xt_k<<<dim3(288, 8, 4), 256>>>(x);
    vsum_k<<<BH, 32>>>(wv);
    qkv_mms<<<dim3(288, 2, 3), 256>>>();
    k_mms<<<dim3(8, BH), 256, 111616>>>(proj);
    k_final<<<BH, 128>>>();
    q_mms<<<dim3(18, BH), 256, 112640>>>(proj);
    out_mms<<<dim3(288, 4), 256>>>(out);
}

// round 13
// speedup vs baseline: 1.1455x; 1.0798x over previous
#include <cuda_runtime.h>
#include <cuda_bf16.h>
#include <math.h>
#include <cstdint>

#define NTOK 9216
#define BATCH 4
#define CHN 256
#define HEADS 8
#define DH 32
#define NB 128
#define BH (BATCH*HEADS)
#define MTOT (BATCH*NTOK)

#define DN 0.4204482076268573f
#define HALF_DN2 0.08838834764831845f
#define RATIO 0.08838834764831845f
#define FEPS 1e-4f

static __device__ float d_q[MTOT*CHN];
static __device__ float d_k[MTOT*CHN];
static __device__ float d_v[MTOT*CHN];
static __device__ float d_ctxe[(size_t)BH*128*33];  // [bh][feat][0..31=ctx, 32=ksum]
static __device__ float d_vsum[BH*DH];
static __device__ float d_xsum[BATCH*CHN];
static __device__ float d_kmax[BH];
static __device__ float d_bcomb[CHN];

static __device__ __nv_bfloat16 d_xth[(size_t)MTOT*CHN];
static __device__ __nv_bfloat16 d_xtl[(size_t)MTOT*CHN];
static __device__ __nv_bfloat16 d_w3h[3*CHN*CHN];
static __device__ __nv_bfloat16 d_w3l[3*CHN*CHN];
static __device__ __nv_bfloat16 d_ath[(size_t)MTOT*CHN];
static __device__ __nv_bfloat16 d_atl[(size_t)MTOT*CHN];
static __device__ __nv_bfloat16 d_wch[CHN*CHN];
static __device__ __nv_bfloat16 d_wcl[CHN*CHN];
static __device__ __nv_bfloat16 d_ctxTh[BH*40*128];  // [bh][row 0..31=ctx_d, 32=ksum, 33..39=0][feat]
static __device__ __nv_bfloat16 d_ctxTl[BH*40*128];

// ---- mma helpers ----
__device__ __forceinline__ uint32_t smem_u32(const void* p) {
    uint32_t a;
    asm("{ .reg .u64 t; cvta.to.shared.u64 t, %1; cvt.u32.u64 %0, t; }" : "=r"(a) : "l"(p));
    return a;
}
__device__ __forceinline__ void cp16(uint32_t saddr, const void* gptr) {
    asm volatile("cp.async.cg.shared.global [%0], [%1], 16;" :: "r"(saddr), "l"(gptr) : "memory");
}
__device__ __forceinline__ void ldsm_x4(uint32_t* r, uint32_t addr) {
    asm volatile("ldmatrix.sync.aligned.m8n8.x4.shared.b16 {%0,%1,%2,%3}, [%4];"
        : "=r"(r[0]), "=r"(r[1]), "=r"(r[2]), "=r"(r[3]) : "r"(addr));
}
__device__ __forceinline__ void ldsm_x2(uint32_t* r, uint32_t addr) {
    asm volatile("ldmatrix.sync.aligned.m8n8.x2.shared.b16 {%0,%1}, [%2];"
        : "=r"(r[0]), "=r"(r[1]) : "r"(addr));
}
__device__ __forceinline__ void ldsm_x4_t(uint32_t* r, uint32_t addr) {
    asm volatile("ldmatrix.sync.aligned.m8n8.x4.trans.shared.b16 {%0,%1,%2,%3}, [%4];"
        : "=r"(r[0]), "=r"(r[1]), "=r"(r[2]), "=r"(r[3]) : "r"(addr));
}
__device__ __forceinline__ void ldsm_x2_t(uint32_t* r, uint32_t addr) {
    asm volatile("ldmatrix.sync.aligned.m8n8.x2.trans.shared.b16 {%0,%1}, [%2];"
        : "=r"(r[0]), "=r"(r[1]) : "r"(addr));
}
__device__ __forceinline__ void mma16816(float* c, const uint32_t* a, const uint32_t* b) {
    asm volatile("mma.sync.aligned.m16n8k16.row.col.f32.bf16.bf16.f32 "
        "{%0,%1,%2,%3}, {%4,%5,%6,%7}, {%8,%9}, {%0,%1,%2,%3};"
        : "+f"(c[0]), "+f"(c[1]), "+f"(c[2]), "+f"(c[3])
        : "r"(a[0]), "r"(a[1]), "r"(a[2]), "r"(a[3]), "r"(b[0]), "r"(b[1]));
}
__device__ __forceinline__ void atomicMaxFloat(float* addr, float val) {
    int* ai = (int*)addr;
    int old = __float_as_int(*addr);
    while (__int_as_float(old) < val) {
        int assumed = old;
        old = atomicCAS(ai, assumed, __float_as_int(val));
        if (old == assumed) break;
    }
}
__device__ __forceinline__ void split_bf16(float v, __nv_bfloat16& h, __nv_bfloat16& l) {
    h = __float2bfloat16_rn(v);
    l = __float2bfloat16_rn(v - __bfloat162float(h));
}
__device__ __forceinline__ void split2pack(float a, float b, uint32_t& hi, uint32_t& lo) {
    __nv_bfloat16 ha = __float2bfloat16_rn(a);
    __nv_bfloat16 hb = __float2bfloat16_rn(b);
    __nv_bfloat16 la = __float2bfloat16_rn(a - __bfloat162float(ha));
    __nv_bfloat16 lb = __float2bfloat16_rn(b - __bfloat162float(hb));
    hi = (uint32_t)(*(unsigned short*)&ha) | ((uint32_t)(*(unsigned short*)&hb) << 16);
    lo = (uint32_t)(*(unsigned short*)&la) | ((uint32_t)(*(unsigned short*)&lb) << 16);
}

// ---------------------------------------------------------------------------
__global__ void init_k() {
    int i = blockIdx.x * 256 + threadIdx.x;
    if (i < BH*128*33) d_ctxe[i] = 0.0f;
    if (i < BATCH*CHN) d_xsum[i] = 0.0f;
    if (i < BH)        d_kmax[i] = -INFINITY;
}

__global__ __launch_bounds__(256) void conv_w(const float* __restrict__ wq,
                                              const float* __restrict__ wk,
                                              const float* __restrict__ wv) {
    int z = blockIdx.y, o = blockIdx.x, c = threadIdx.x;
    const float* W = (z == 0) ? wq : ((z == 1) ? wk : wv);
    float v = W[o*CHN + c];
    __nv_bfloat16 h, l; split_bf16(v, h, l);
    d_w3h[(z*CHN + o)*CHN + c] = h;
    d_w3l[(z*CHN + o)*CHN + c] = l;
}

__global__ __launch_bounds__(256) void wcomb_k(const float* __restrict__ wo,
                                               const float* __restrict__ bo,
                                               const float* __restrict__ wp,
                                               const float* __restrict__ bp) {
    int o = blockIdx.x, c = threadIdx.x;
    float acc = 0.0f;
    for (int j = 0; j < CHN; j++) acc += wp[o*CHN + j] * wo[j*CHN + c];
    __nv_bfloat16 h, l; split_bf16(acc, h, l);
    d_wch[o*CHN + c] = h;
    d_wcl[o*CHN + c] = l;
    if (c == 0) {
        float bcc = 0.0f;
        for (int j = 0; j < CHN; j++) bcc += wp[o*CHN + j] * bo[j];
        d_bcomb[o] = bcc + bp[o];
    }
}

// ---------------------------------------------------------------------------
// transpose x -> bf16 hi/lo + accumulate xsum[b][c]
// ---------------------------------------------------------------------------
__global__ __launch_bounds__(256) void xt_k(const float* __restrict__ x) {
    __shared__ float ts[32][33];
    int b = blockIdx.z, c0 = blockIdx.y * 32, p0 = blockIdx.x * 32;
    int tid = threadIdx.x;
    int tx = tid & 31, ty = tid >> 5;
    #pragma unroll
    for (int i = 0; i < 4; i++) {
        int c = c0 + ty + i*8;
        ts[ty + i*8][tx] = x[((size_t)(b*CHN + c))*NTOK + p0 + tx];
    }
    __syncthreads();
    {
        int cl = tid >> 3, j0 = (tid & 7)*4;
        float s = ts[cl][j0] + ts[cl][j0+1] + ts[cl][j0+2] + ts[cl][j0+3];
        s += __shfl_xor_sync(0xffffffffu, s, 1);
        s += __shfl_xor_sync(0xffffffffu, s, 2);
        s += __shfl_xor_sync(0xffffffffu, s, 4);
        if ((tid & 7) == 0) atomicAdd(&d_xsum[b*CHN + c0 + cl], s);
    }
    #pragma unroll
    for (int i = 0; i < 4; i++) {
        int p = p0 + ty + i*8;
        float v = ts[tx][ty + i*8];
        size_t gi = (size_t)(b*NTOK + p)*CHN + c0 + tx;
        __nv_bfloat16 h, l; split_bf16(v, h, l);
        d_xth[gi] = h;
        d_xtl[gi] = l;
    }
}

__global__ __launch_bounds__(32) void vsum_k(const float* __restrict__ wv) {
    int bh = blockIdx.x, d = threadIdx.x;
    int b = bh >> 3, hd = bh & 7;
    const float* xs = &d_xsum[b*CHN];
    const float* wr = &wv[(hd*32 + d)*CHN];
    float s = 0.0f;
    for (int c = 0; c < CHN; c++) s += xs[c]*wr[c];
    d_vsum[bh*32 + d] = s;
}

// ---------------------------------------------------------------------------
// QKV GEMM via mma.sync (round-10 tiling 128x64) + cp.async double buffering
// ---------------------------------------------------------------------------
__global__ __launch_bounds__(256) void qkv_mms() {
    extern __shared__ char qsm[];
    uint32_t sb = smem_u32(qsm);
    const int BUF = 30720, AHo = 0, ALo = 10240, BHo = 20480, BLo = 25600;

    int z = blockIdx.z;
    const __nv_bfloat16* WH = d_w3h + (size_t)z*CHN*CHN;
    const __nv_bfloat16* WL = d_w3l + (size_t)z*CHN*CHN;
    float* C = (z == 0) ? d_q : ((z == 1) ? d_k : d_v);
    int m0 = blockIdx.x * 128, n0 = blockIdx.y * 64;
    int tid = threadIdx.x, wid = tid >> 5, lane = tid & 31;
    int wm = (wid & 3) * 32, wn = (wid >> 2) * 32;

    float acc[2][4][4];
    #pragma unroll
    for (int mi = 0; mi < 2; mi++)
        #pragma unroll
        for (int ni = 0; ni < 4; ni++)
            #pragma unroll
            for (int q = 0; q < 4; q++) acc[mi][ni][q] = 0.0f;

    int arow = wm + (lane & 15);
    int acol8 = (lane >> 4) * 8;
    int brow = wn + ((lane >> 4) << 3) + (lane & 7);
    int bcol8 = ((lane >> 3) & 1) * 8;

    auto issue_chunk = [&](int ck, int buf) {
        int k0 = ck * 32;
        uint32_t base = sb + buf*BUF;
        #pragma unroll
        for (int j = 0; j < 2; j++) {
            int i = tid + j*256, row = i >> 2, cg = i & 3;
            size_t g = (size_t)(m0 + row)*CHN + k0 + cg*8;
            uint32_t so = (uint32_t)(row*80 + cg*16);
            cp16(base + AHo + so, d_xth + g);
            cp16(base + ALo + so, d_xtl + g);
        }
        {
            int row = tid >> 2, cg = tid & 3;
            size_t g = (size_t)(n0 + row)*CHN + k0 + cg*8;
            uint32_t so = (uint32_t)(row*80 + cg*16);
            cp16(base + BHo + so, WH + g);
            cp16(base + BLo + so, WL + g);
        }
        asm volatile("cp.async.commit_group;" ::: "memory");
    };

    issue_chunk(0, 0);
    for (int ck = 0; ck < 8; ck++) {
        int buf = ck & 1;
        if (ck < 7) {
            issue_chunk(ck + 1, buf ^ 1);
            asm volatile("cp.async.wait_group 1;" ::: "memory");
        } else {
            asm volatile("cp.async.wait_group 0;" ::: "memory");
        }
        __syncthreads();
        uint32_t base = sb + buf*BUF;
        #pragma unroll
        for (int ks = 0; ks < 32; ks += 16) {
            uint32_t ah[2][4], al[2][4], bh[2][4], bl[2][4];
            #pragma unroll
            for (int mi = 0; mi < 2; mi++) {
                uint32_t aa = base + AHo + (uint32_t)((arow + mi*16)*80 + (ks + acol8)*2);
                ldsm_x4(ah[mi], aa);
                ldsm_x4(al[mi], aa + (ALo - AHo));
            }
            #pragma unroll
            for (int p = 0; p < 2; p++) {
                uint32_t ba = base + BHo + (uint32_t)((brow + p*16)*80 + (ks + bcol8)*2);
                ldsm_x4(bh[p], ba);
                ldsm_x4(bl[p], ba + (BLo - BHo));
            }
            #pragma unroll
            for (int mi = 0; mi < 2; mi++)
                #pragma unroll
                for (int ni = 0; ni < 4; ni++) {
                    const uint32_t* bhp = &bh[ni >> 1][(ni & 1)*2];
                    const uint32_t* blp = &bl[ni >> 1][(ni & 1)*2];
                    mma16816(acc[mi][ni], ah[mi], bhp);
                    mma16816(acc[mi][ni], ah[mi], blp);
                    mma16816(acc[mi][ni], al[mi], bhp);
                }
        }
        __syncthreads();
    }
    #pragma unroll
    for (int mi = 0; mi < 2; mi++)
        #pragma unroll
        for (int ni = 0; ni < 4; ni++) {
            int m = m0 + wm + mi*16 + (lane >> 2);
            int n = n0 + wn + ni*8 + 2*(lane & 3);
            *(float2*)&C[(size_t)m*CHN + n]     = make_float2(acc[mi][ni][0], acc[mi][ni][1]);
            *(float2*)&C[(size_t)(m+8)*CHN + n] = make_float2(acc[mi][ni][2], acc[mi][ni][3]);
        }
}

// ---------------------------------------------------------------------------
// k path via mma.sync. smem aliased: K tile lives inside E region.
// ---------------------------------------------------------------------------
__global__ __launch_bounds__(256, 2) void k_mms(const float* __restrict__ proj) {
    extern __shared__ char sm[];
    const int PH=0, PL=10240, VH=20480, VL=30720,
              EH=40960, EL=75776,           // E: [40960, 110592)
              KH=40960, KL=51200,           // K aliased inside E
              DG=110592, RED=111104;
    uint32_t sb = smem_u32(sm);
    int bh = blockIdx.y, chunk = blockIdx.x;
    int b = bh >> 3, hd = bh & 7;
    int tid = threadIdx.x, wid = tid >> 5, lane = tid & 31;
    int lrow = tid >> 1, lhalf = tid & 1;
    int wtok = wid * 16, wf = wid * 16;

    {
        const float4* p4 = (const float4*)(proj + lrow*32 + lhalf*16);
        #pragma unroll
        for (int i = 0; i < 4; i++) {
            float4 f = p4[i];
            uint32_t h0, l0, h1, l1;
            split2pack(f.x, f.y, h0, l0);
            split2pack(f.z, f.w, h1, l1);
            int co = lrow*80 + lhalf*32 + i*8;
            *(uint2*)(sm + PH + co) = make_uint2(h0, h1);
            *(uint2*)(sm + PL + co) = make_uint2(l0, l1);
        }
    }

    float lmax = -INFINITY;
    float acc2[5][4];
    #pragma unroll
    for (int i = 0; i < 5; i++)
        #pragma unroll
        for (int j = 0; j < 4; j++) acc2[i][j] = 0.0f;

    for (int tile = 0; tile < 9; tile++) {
        int p0 = chunk*1152 + tile*128;
        {
            size_t g = ((size_t)(b*NTOK + p0 + lrow))*CHN + hd*32 + lhalf*16;
            const float4* k4 = (const float4*)(d_k + g);
            const float4* v4 = (const float4*)(d_v + g);
            float sq = 0.0f;
            #pragma unroll
            for (int i = 0; i < 4; i++) {
                float4 kf = k4[i];
                sq += kf.x*kf.x + kf.y*kf.y + kf.z*kf.z + kf.w*kf.w;
                uint32_t h0, l0, h1, l1;
                split2pack(kf.x, kf.y, h0, l0); split2pack(kf.z, kf.w, h1, l1);
                int co = lrow*80 + lhalf*32 + i*8;
                *(uint2*)(sm + KH + co) = make_uint2(h0, h1);
                *(uint2*)(sm + KL + co) = make_uint2(l0, l1);
                float4 vf = v4[i];
                split2pack(vf.x, vf.y, h0, l0); split2pack(vf.z, vf.w, h1, l1);
                *(uint2*)(sm + VH + co) = make_uint2(h0, h1);
                *(uint2*)(sm + VL + co) = make_uint2(l0, l1);
            }
            sq += __shfl_xor_sync(0xffffffffu, sq, 1);
            if (lhalf == 0) {
                ((float*)(sm + DG))[lrow] = sq * HALF_DN2;
            } else {
                *(uint4*)(sm + VH + lrow*80 + 64) = make_uint4(0x00003F80u, 0u, 0u, 0u);
                *(uint4*)(sm + VL + lrow*80 + 64) = make_uint4(0u, 0u, 0u, 0u);
            }
        }
        __syncthreads();

        float acc1[16][4];
        #pragma unroll
        for (int i = 0; i < 16; i++)
            #pragma unroll
            for (int j = 0; j < 4; j++) acc1[i][j] = 0.0f;
        #pragma unroll
        for (int ks = 0; ks < 32; ks += 16) {
            uint32_t ah[4], al[4];
            uint32_t aa = sb + KH + (wtok + (lane & 15))*80 + (ks + ((lane >> 4) << 3))*2;
            ldsm_x4(ah, aa);
            ldsm_x4(al, aa + (KL - KH));
            #pragma unroll
            for (int g = 0; g < 8; g++) {
                uint32_t bhf[4], blf[4];
                uint32_t ba = sb + PH + (g*16 + ((lane >> 4) << 3) + (lane & 7))*80
                                      + (ks + (((lane >> 3) & 1) << 3))*2;
                ldsm_x4(bhf, ba);
                ldsm_x4(blf, ba + (PL - PH));
                #pragma unroll
                for (int h = 0; h < 2; h++) {
                    float* c = acc1[g*2 + h];
                    mma16816(c, ah, &bhf[h*2]);
                    mma16816(c, ah, &blf[h*2]);
                    mma16816(c, al, &bhf[h*2]);
                }
            }
        }
        __syncthreads();   // all warps done reading K before E overwrites it
        {
            int r0 = wtok + (lane >> 2), cq = 2*(lane & 3);
            float dg0 = ((float*)(sm + DG))[r0];
            float dg1 = ((float*)(sm + DG))[r0 + 8];
            #pragma unroll
            for (int f = 0; f < 16; f++) {
                int c0 = f*8 + cq;
                float v0 = acc1[f][0]*DN, v1 = acc1[f][1]*DN;
                float v2 = acc1[f][2]*DN, v3 = acc1[f][3]*DN;
                lmax = fmaxf(lmax, fmaxf(fmaxf(v0, v1), fmaxf(v2, v3)));
                uint32_t h0, l0, h1, l1;
                split2pack(__expf(v0 - dg0), __expf(v1 - dg0), h0, l0);
                split2pack(__expf(v2 - dg1), __expf(v3 - dg1), h1, l1);
                *(uint32_t*)(sm + EH + r0*272 + c0*2)       = h0;
                *(uint32_t*)(sm + EL + r0*272 + c0*2)       = l0;
                *(uint32_t*)(sm + EH + (r0 + 8)*272 + c0*2) = h1;
                *(uint32_t*)(sm + EL + (r0 + 8)*272 + c0*2) = l1;
            }
        }
        __syncthreads();

        #pragma unroll
        for (int kk = 0; kk < 8; kk++) {
            int tok0 = kk*16;
            uint32_t eh[4], el[4];
            uint32_t aa = sb + EH + (tok0 + ((lane >> 4) << 3) + (lane & 7))*272
                                  + (wf + (((lane >> 3) & 1) << 3))*2;
            ldsm_x4_t(eh, aa);
            ldsm_x4_t(el, aa + (EL - EH));
            uint32_t vrowb = sb + VH + (tok0 + (((lane >> 3) & 1) << 3) + (lane & 7))*80;
            uint32_t doff = ((lane >> 4) << 3)*2;
            uint32_t vh0[4], vl0[4], vh1[4], vl1[4], v2h[2], v2l[2];
            ldsm_x4_t(vh0, vrowb + doff);
            ldsm_x4_t(vl0, vrowb + (VL - VH) + doff);
            ldsm_x4_t(vh1, vrowb + 32 + doff);
            ldsm_x4_t(vl1, vrowb + (VL - VH) + 32 + doff);
            ldsm_x2_t(v2h, vrowb + 64);
            ldsm_x2_t(v2l, vrowb + (VL - VH) + 64);
            const uint32_t* bhf[5] = {&vh0[0], &vh0[2], &vh1[0], &vh1[2], &v2h[0]};
            const uint32_t* blf[5] = {&vl0[0], &vl0[2], &vl1[0], &vl1[2], &v2l[0]};
            #pragma unroll
            for (int nf = 0; nf < 5; nf++) {
                mma16816(acc2[nf], eh, bhf[nf]);
                mma16816(acc2[nf], eh, blf[nf]);
                mma16816(acc2[nf], el, bhf[nf]);
            }
        }
        __syncthreads();
    }

    #pragma unroll
    for (int off = 16; off > 0; off >>= 1)
        lmax = fmaxf(lmax, __shfl_xor_sync(0xffffffffu, lmax, off));
    if (lane == 0) ((float*)(sm + RED))[wid] = lmax;
    __syncthreads();
    if (tid == 0) {
        float m = ((float*)(sm + RED))[0];
        #pragma unroll
        for (int i = 1; i < 8; i++) m = fmaxf(m, ((float*)(sm + RED))[i]);
        atomicMaxFloat(&d_kmax[bh], m);
    }
    {
        int r0 = wf + (lane >> 2), cq = 2*(lane & 3);
        #pragma unroll
        for (int nf = 0; nf < 4; nf++) {
            int c0 = nf*8 + cq;
            float* pa = &d_ctxe[((size_t)bh*128 + r0)*33 + c0];
            float* pb = &d_ctxe[((size_t)bh*128 + r0 + 8)*33 + c0];
            atomicAdd(pa,     acc2[nf][0]); atomicAdd(pa + 1, acc2[nf][1]);
            atomicAdd(pb,     acc2[nf][2]); atomicAdd(pb + 1, acc2[nf][3]);
        }
        if ((lane & 3) == 0) {
            atomicAdd(&d_ctxe[((size_t)bh*128 + r0)*33 + 32],     acc2[4][0]);
            atomicAdd(&d_ctxe[((size_t)bh*128 + r0 + 8)*33 + 32], acc2[4][2]);
        }
    }
}

// ---------------------------------------------------------------------------
// finalize -> transposed augmented ctxT bf16 hi/lo
// ---------------------------------------------------------------------------
__global__ __launch_bounds__(128) void k_final() {
    int bh = blockIdx.x, t = threadIdx.x;  // t = feat
    float scale = __expf(-d_kmax[bh]);
    const float* ce = &d_ctxe[((size_t)bh*128 + t)*33];
    size_t tb = (size_t)bh*40*128 + t;
    #pragma unroll
    for (int d = 0; d < 32; d++) {
        float cf = RATIO * (scale * ce[d] + FEPS * d_vsum[bh*DH + d]);
        __nv_bfloat16 h, l; split_bf16(cf, h, l);
        d_ctxTh[tb + d*128] = h;
        d_ctxTl[tb + d*128] = l;
    }
    {
        float ks = RATIO * (scale * ce[32] + FEPS * (float)NTOK);
        __nv_bfloat16 h, l; split_bf16(ks, h, l);
        d_ctxTh[tb + 32*128] = h;
        d_ctxTl[tb + 32*128] = l;
    }
    __nv_bfloat16 z = __float2bfloat16_rn(0.0f);
    #pragma unroll
    for (int d = 33; d < 40; d++) {
        d_ctxTh[tb + d*128] = z;
        d_ctxTl[tb + d*128] = z;
    }
}

// ---------------------------------------------------------------------------
// q path via mma.sync. smem aliased: Q tile inside E region.
// ---------------------------------------------------------------------------
__global__ __launch_bounds__(256, 2) void q_mms(const float* __restrict__ proj) {
    extern __shared__ char sm[];
    const int PH=0, PL=10240, CTH=20480, CTL=31360,
              EH=42240, EL=77056,          // E: [42240, 111872)
              QH=42240, QL=52480,          // Q aliased inside E
              DG=111872;
    uint32_t sb = smem_u32(sm);
    int bh = blockIdx.y, chunk = blockIdx.x;
    int b = bh >> 3, hd = bh & 7;
    int tid = threadIdx.x, wid = tid >> 5, lane = tid & 31;
    int lrow = tid >> 1, lhalf = tid & 1;
    int wtok = wid * 16;

    // proj -> smem
    {
        const float4* p4 = (const float4*)(proj + lrow*32 + lhalf*16);
        #pragma unroll
        for (int i = 0; i < 4; i++) {
            float4 f = p4[i];
            uint32_t h0, l0, h1, l1;
            split2pack(f.x, f.y, h0, l0);
            split2pack(f.z, f.w, h1, l1);
            int co = lrow*80 + lhalf*32 + i*8;
            *(uint2*)(sm + PH + co) = make_uint2(h0, h1);
            *(uint2*)(sm + PL + co) = make_uint2(l0, l1);
        }
    }
    // ctxT -> smem (40 rows x 128 cols = 16 uint4 groups per row, stride 272B)
    {
        const uint4* gh = (const uint4*)(d_ctxTh + (size_t)bh*40*128);
        const uint4* gl = (const uint4*)(d_ctxTl + (size_t)bh*40*128);
        #pragma unroll
        for (int j = 0; j < 3; j++) {
            int idx = tid + j*256;
            if (idx < 640) {
                int row = idx >> 4, cg = idx & 15;
                *(uint4*)(sm + CTH + row*272 + cg*16) = gh[idx];
                *(uint4*)(sm + CTL + row*272 + cg*16) = gl[idx];
            }
        }
    }

    for (int tile = 0; tile < 4; tile++) {
        int p0 = chunk*512 + tile*128;
        // load q tile + diag
        {
            size_t g = ((size_t)(b*NTOK + p0 + lrow))*CHN + hd*32 + lhalf*16;
            const float4* q4 = (const float4*)(d_q + g);
            float sq = 0.0f;
            #pragma unroll
            for (int i = 0; i < 4; i++) {
                float4 qf = q4[i];
                sq += qf.x*qf.x + qf.y*qf.y + qf.z*qf.z + qf.w*qf.w;
                uint32_t h0, l0, h1, l1;
                split2pack(qf.x, qf.y, h0, l0); split2pack(qf.z, qf.w, h1, l1);
                int co = lrow*80 + lhalf*32 + i*8;
                *(uint2*)(sm + QH + co) = make_uint2(h0, h1);
                *(uint2*)(sm + QL + co) = make_uint2(l0, l1);
            }
            sq += __shfl_xor_sync(0xffffffffu, sq, 1);
            if (lhalf == 0) ((float*)(sm + DG))[lrow] = sq * HALF_DN2;
        }
        __syncthreads();

        // MMA1: dash = q . projT
        float acc1[16][4];
        #pragma unroll
        for (int i = 0; i < 16; i++)
            #pragma unroll
            for (int j = 0; j < 4; j++) acc1[i][j] = 0.0f;
        #pragma unroll
        for (int ks = 0; ks < 32; ks += 16) {
            uint32_t ah[4], al[4];
            uint32_t aa = sb + QH + (wtok + (lane & 15))*80 + (ks + ((lane >> 4) << 3))*2;
            ldsm_x4(ah, aa);
            ldsm_x4(al, aa + (QL - QH));
            #pragma unroll
            for (int g = 0; g < 8; g++) {
                uint32_t bhf[4], blf[4];
                uint32_t ba = sb + PH + (g*16 + ((lane >> 4) << 3) + (lane & 7))*80
                                      + (ks + (((lane >> 3) & 1) << 3))*2;
                ldsm_x4(bhf, ba);
                ldsm_x4(blf, ba + (PL - PH));
                #pragma unroll
                for (int h = 0; h < 2; h++) {
                    float* c = acc1[g*2 + h];
                    mma16816(c, ah, &bhf[h*2]);
                    mma16816(c, ah, &blf[h*2]);
                    mma16816(c, al, &bhf[h*2]);
                }
            }
        }
        __syncthreads();   // all warps done reading Q before E overwrites it
        // epilogue 1: per-token max, qp = ratio*(exp(...)+eps)
        {
            int r0 = wtok + (lane >> 2);
            float dg0 = ((float*)(sm + DG))[r0];
            float dg1 = ((float*)(sm + DG))[r0 + 8];
            float mx0 = -INFINITY, mx1 = -INFINITY;
            #pragma unroll
            for (int f = 0; f < 16; f++) {
                mx0 = fmaxf(mx0, fmaxf(acc1[f][0], acc1[f][1]));
                mx1 = fmaxf(mx1, fmaxf(acc1[f][2], acc1[f][3]));
            }
            mx0 = fmaxf(mx0, __shfl_xor_sync(0xffffffffu, mx0, 1));
            mx0 = fmaxf(mx0, __shfl_xor_sync(0xffffffffu, mx0, 2));
            mx1 = fmaxf(mx1, __shfl_xor_sync(0xffffffffu, mx1, 1));
            mx1 = fmaxf(mx1, __shfl_xor_sync(0xffffffffu, mx1, 2));
            mx0 = mx0*DN + dg0;
            mx1 = mx1*DN + dg1;
            int cq = 2*(lane & 3);
            #pragma unroll
            for (int f = 0; f < 16; f++) {
                int c0 = f*8 + cq;
                float e0 = RATIO*(__expf(acc1[f][0]*DN - mx0) + FEPS);
                float e1 = RATIO*(__expf(acc1[f][1]*DN - mx0) + FEPS);
                float e2 = RATIO*(__expf(acc1[f][2]*DN - mx1) + FEPS);
                float e3 = RATIO*(__expf(acc1[f][3]*DN - mx1) + FEPS);
                uint32_t h0, l0, h1, l1;
                split2pack(e0, e1, h0, l0);
                split2pack(e2, e3, h1, l1);
                *(uint32_t*)(sm + EH + r0*272 + c0*2)       = h0;
                *(uint32_t*)(sm + EL + r0*272 + c0*2)       = l0;
                *(uint32_t*)(sm + EH + (r0 + 8)*272 + c0*2) = h1;
                *(uint32_t*)(sm + EL + (r0 + 8)*272 + c0*2) = l1;
            }
        }
        __syncthreads();

        // MMA2: out[16tok][40] = qp . ctxT_aug
        float acc2[5][4];
        #pragma unroll
        for (int i = 0; i < 5; i++)
            #pragma unroll
            for (int j = 0; j < 4; j++) acc2[i][j] = 0.0f;
        #pragma unroll
        for (int ks = 0; ks < 128; ks += 16) {
            uint32_t eh[4], el[4];
            uint32_t aa = sb + EH + (wtok + (lane & 15))*272 + (ks + ((lane >> 4) << 3))*2;
            ldsm_x4(eh, aa);
            ldsm_x4(el, aa + (EL - EH));
            uint32_t b0 = sb + CTH + (((lane >> 4) << 3) + (lane & 7))*272
                                   + (ks + (((lane >> 3) & 1) << 3))*2;
            uint32_t c0h[4], c0l[4], c1h[4], c1l[4], c2h[2], c2l[2];
            ldsm_x4(c0h, b0);
            ldsm_x4(c0l, b0 + (CTL - CTH));
            ldsm_x4(c1h, b0 + 16*272);
            ldsm_x4(c1l, b0 + (CTL - CTH) + 16*272);
            {
                uint32_t b2 = sb + CTH + (32 + (lane & 7))*272
                                       + (ks + (((lane >> 3) & 1) << 3))*2;
                ldsm_x2(c2h, b2);
                ldsm_x2(c2l, b2 + (CTL - CTH));
            }
            const uint32_t* bhf[5] = {&c0h[0], &c0h[2], &c1h[0], &c1h[2], &c2h[0]};
            const uint32_t* blf[5] = {&c0l[0], &c0l[2], &c1l[0], &c1l[2], &c2l[0]};
            #pragma unroll
            for (int nf = 0; nf < 5; nf++) {
                mma16816(acc2[nf], eh, bhf[nf]);
                mma16816(acc2[nf], eh, blf[nf]);
                mma16816(acc2[nf], el, bhf[nf]);
            }
        }
        // epilogue 2: dinv from col 32, write attn bf16 hi/lo
        {
            int r0 = wtok + (lane >> 2), cq = 2*(lane & 3);
            int src = lane & ~3;
            float den0 = __shfl_sync(0xffffffffu, acc2[4][0], src);
            float den1 = __shfl_sync(0xffffffffu, acc2[4][2], src);
            float di0 = 1.0f / den0, di1 = 1.0f / den1;
            size_t g0 = (size_t)(b*NTOK + p0 + r0)*CHN + hd*32;
            size_t g1 = g0 + (size_t)8*CHN;
            #pragma unroll
            for (int nf = 0; nf < 4; nf++) {
                int c0 = nf*8 + cq;
                uint32_t h0, l0, h1, l1;
                split2pack(acc2[nf][0]*di0, acc2[nf][1]*di0, h0, l0);
                split2pack(acc2[nf][2]*di1, acc2[nf][3]*di1, h1, l1);
                *(uint32_t*)(d_ath + g0 + c0) = h0;
                *(uint32_t*)(d_atl + g0 + c0) = l0;
                *(uint32_t*)(d_ath + g1 + c0) = h1;
                *(uint32_t*)(d_atl + g1 + c0) = l1;
            }
        }
        __syncthreads();
    }
}

// ---------------------------------------------------------------------------
// output GEMM via mma.sync (unchanged, passing)
// ---------------------------------------------------------------------------
__global__ __launch_bounds__(256) void out_mms(float* __restrict__ out) {
    __shared__ __align__(16) char smraw[34816];
    __nv_bfloat16 (*Ah)[40] = (__nv_bfloat16(*)[40])(smraw);
    __nv_bfloat16 (*Al)[40] = (__nv_bfloat16(*)[40])(smraw + 10240);
    __nv_bfloat16 (*Bh)[40] = (__nv_bfloat16(*)[40])(smraw + 20480);
    __nv_bfloat16 (*Bl)[40] = (__nv_bfloat16(*)[40])(smraw + 25600);
    float (*Ct)[132] = (float(*)[132])(smraw);

    int m0 = blockIdx.x * 128, n0 = blockIdx.y * 64;
    int tid = threadIdx.x, wid = tid >> 5, lane = tid & 31;
    int wm = (wid & 3) * 32, wn = (wid >> 2) * 32;

    float acc[2][4][4];
    #pragma unroll
    for (int mi = 0; mi < 2; mi++)
        #pragma unroll
        for (int ni = 0; ni < 4; ni++)
            #pragma unroll
            for (int q = 0; q < 4; q++) acc[mi][ni][q] = 0.0f;

    int arow = wm + (lane & 15);
    int acol8 = (lane >> 4) * 8;
    int brow = wn + ((lane >> 4) << 3) + (lane & 7);
    int bcol8 = ((lane >> 3) & 1) * 8;

    for (int ck = 0; ck < 8; ck++) {
        int k0 = ck * 32;
        #pragma unroll
        for (int j = 0; j < 2; j++) {
            int i = tid + j*256, row = i >> 2, cg = i & 3;
            size_t g = (size_t)(m0 + row)*CHN + k0 + cg*8;
            *(uint4*)&Ah[row][cg*8] = *(const uint4*)(d_ath + g);
            *(uint4*)&Al[row][cg*8] = *(const uint4*)(d_atl + g);
        }
        {
            int row = tid >> 2, cg = tid & 3;
            size_t g = (size_t)(n0 + row)*CHN + k0 + cg*8;
            *(uint4*)&Bh[row][cg*8] = *(const uint4*)(d_wch + g);
            *(uint4*)&Bl[row][cg*8] = *(const uint4*)(d_wcl + g);
        }
        __syncthreads();
        #pragma unroll
        for (int ks = 0; ks < 32; ks += 16) {
            uint32_t ah[2][4], al[2][4], bh[2][4], bl[2][4];
            #pragma unroll
            for (int mi = 0; mi < 2; mi++) {
                ldsm_x4(ah[mi], smem_u32(&Ah[arow + mi*16][ks + acol8]));
                ldsm_x4(al[mi], smem_u32(&Al[arow + mi*16][ks + acol8]));
            }
            #pragma unroll
            for (int p = 0; p < 2; p++) {
                ldsm_x4(bh[p], smem_u32(&Bh[brow + p*16][ks + bcol8]));
                ldsm_x4(bl[p], smem_u32(&Bl[brow + p*16][ks + bcol8]));
            }
            #pragma unroll
            for (int mi = 0; mi < 2; mi++)
                #pragma unroll
                for (int ni = 0; ni < 4; ni++) {
                    const uint32_t* bhp = &bh[ni >> 1][(ni & 1)*2];
                    const uint32_t* blp = &bl[ni >> 1][(ni & 1)*2];
                    mma16816(acc[mi][ni], ah[mi], bhp);
                    mma16816(acc[mi][ni], ah[mi], blp);
                    mma16816(acc[mi][ni], al[mi], bhp);
                }
        }
        __syncthreads();
    }

    #pragma unroll
    for (int mi = 0; mi < 2; mi++)
        #pragma unroll
        for (int ni = 0; ni < 4; ni++) {
            int ml = wm + mi*16 + (lane >> 2);
            int nl = wn + ni*8 + 2*(lane & 3);
            Ct[nl][ml]       = acc[mi][ni][0];
            Ct[nl+1][ml]     = acc[mi][ni][1];
            Ct[nl][ml+8]     = acc[mi][ni][2];
            Ct[nl+1][ml+8]   = acc[mi][ni][3];
        }
    __syncthreads();

    int bb = m0 / NTOK, ptok = m0 % NTOK;
    int ch = tid >> 2, tg = tid & 3;
    float bias = d_bcomb[n0 + ch];
    size_t rowb = (size_t)(bb*CHN + n0 + ch) * NTOK + ptok;
    #pragma unroll
    for (int j = 0; j < 8; j++) {
        int tl = tg*32 + j*4;
        float4 v = *(float4*)&Ct[ch][tl];
        *(float4*)&out[rowb + tl] = make_float4(v.x+bias, v.y+bias, v.z+bias, v.w+bias);
    }
}

extern "C" void kernel_launch(void* const* d_in, const int* in_sizes, int n_in,
                              void* d_out, int out_size) {
    const float* x    = (const float*)d_in[0];
    const float* wq   = (const float*)d_in[1];
    const float* wk   = (const float*)d_in[2];
    const float* wv   = (const float*)d_in[3];
    const float* wo   = (const float*)d_in[4];
    const float* bo   = (const float*)d_in[5];
    const float* proj = (const float*)d_in[6];
    const float* wp   = (const float*)d_in[7];
    const float* bp   = (const float*)d_in[8];
    float* out = (float*)d_out;

    cudaFuncSetAttribute(qkv_mms, cudaFuncAttributeMaxDynamicSharedMemorySize, 61440);
    cudaFuncSetAttribute(k_mms, cudaFuncAttributeMaxDynamicSharedMemorySize, 111616);
    cudaFuncSetAttribute(q_mms, cudaFuncAttributeMaxDynamicSharedMemorySize, 112640);

    init_k<<<768, 256>>>();
    conv_w<<<dim3(256, 3), 256>>>(wq, wk, wv);
    wcomb_k<<<256, 256>>>(wo, bo, wp, bp);
    xt_k<<<dim3(288, 8, 4), 256>>>(x);
    vsum_k<<<BH, 32>>>(wv);
    qkv_mms<<<dim3(288, 4, 3), 256, 61440>>>();
    k_mms<<<dim3(8, BH), 256, 111616>>>(proj);
    k_final<<<BH, 128>>>();
    q_mms<<<dim3(18, BH), 256, 112640>>>(proj);
    out_mms<<<dim3(288, 4), 256>>>(out);
}

// round 15
// speedup vs baseline: 1.1607x; 1.0132x over previous
#include <cuda_runtime.h>
#include <cuda_bf16.h>
#include <math.h>
#include <cstdint>

#define NTOK 9216
#define BATCH 4
#define CHN 256
#define HEADS 8
#define DH 32
#define NB 128
#define BH (BATCH*HEADS)
#define MTOT (BATCH*NTOK)

#define DN 0.4204482076268573f
#define HALF_DN2 0.08838834764831845f
#define RATIO 0.08838834764831845f
#define FEPS 1e-4f

static __device__ float d_q[MTOT*CHN];
static __device__ float d_k[MTOT*CHN];
static __device__ float d_v[MTOT*CHN];
static __device__ float d_ctxe[(size_t)BH*128*33];  // [bh][feat][0..31=ctx, 32=ksum]
static __device__ float d_vsum[BH*DH];
static __device__ float d_xsum[BATCH*CHN];
static __device__ float d_kmax[BH];
static __device__ float d_bcomb[CHN];

static __device__ __nv_bfloat16 d_xth[(size_t)MTOT*CHN];
static __device__ __nv_bfloat16 d_xtl[(size_t)MTOT*CHN];
static __device__ __nv_bfloat16 d_w3h[3*CHN*CHN];
static __device__ __nv_bfloat16 d_w3l[3*CHN*CHN];
static __device__ __nv_bfloat16 d_ath[(size_t)MTOT*CHN];
static __device__ __nv_bfloat16 d_atl[(size_t)MTOT*CHN];
static __device__ __nv_bfloat16 d_wch[CHN*CHN];
static __device__ __nv_bfloat16 d_wcl[CHN*CHN];
static __device__ __nv_bfloat16 d_ctxTh[BH*40*128];  // [bh][row 0..31=ctx_d, 32=ksum, 33..39=0][feat]
static __device__ __nv_bfloat16 d_ctxTl[BH*40*128];

// ---- mma helpers ----
__device__ __forceinline__ uint32_t smem_u32(const void* p) {
    uint32_t a;
    asm("{ .reg .u64 t; cvta.to.shared.u64 t, %1; cvt.u32.u64 %0, t; }" : "=r"(a) : "l"(p));
    return a;
}
__device__ __forceinline__ void cp16(uint32_t saddr, const void* gptr) {
    asm volatile("cp.async.cg.shared.global [%0], [%1], 16;" :: "r"(saddr), "l"(gptr) : "memory");
}
__device__ __forceinline__ void ldsm_x4(uint32_t* r, uint32_t addr) {
    asm volatile("ldmatrix.sync.aligned.m8n8.x4.shared.b16 {%0,%1,%2,%3}, [%4];"
        : "=r"(r[0]), "=r"(r[1]), "=r"(r[2]), "=r"(r[3]) : "r"(addr));
}
__device__ __forceinline__ void ldsm_x2(uint32_t* r, uint32_t addr) {
    asm volatile("ldmatrix.sync.aligned.m8n8.x2.shared.b16 {%0,%1}, [%2];"
        : "=r"(r[0]), "=r"(r[1]) : "r"(addr));
}
__device__ __forceinline__ void ldsm_x4_t(uint32_t* r, uint32_t addr) {
    asm volatile("ldmatrix.sync.aligned.m8n8.x4.trans.shared.b16 {%0,%1,%2,%3}, [%4];"
        : "=r"(r[0]), "=r"(r[1]), "=r"(r[2]), "=r"(r[3]) : "r"(addr));
}
__device__ __forceinline__ void ldsm_x2_t(uint32_t* r, uint32_t addr) {
    asm volatile("ldmatrix.sync.aligned.m8n8.x2.trans.shared.b16 {%0,%1}, [%2];"
        : "=r"(r[0]), "=r"(r[1]) : "r"(addr));
}
__device__ __forceinline__ void mma16816(float* c, const uint32_t* a, const uint32_t* b) {
    asm volatile("mma.sync.aligned.m16n8k16.row.col.f32.bf16.bf16.f32 "
        "{%0,%1,%2,%3}, {%4,%5,%6,%7}, {%8,%9}, {%0,%1,%2,%3};"
        : "+f"(c[0]), "+f"(c[1]), "+f"(c[2]), "+f"(c[3])
        : "r"(a[0]), "r"(a[1]), "r"(a[2]), "r"(a[3]), "r"(b[0]), "r"(b[1]));
}
__device__ __forceinline__ void atomicMaxFloat(float* addr, float val) {
    int* ai = (int*)addr;
    int old = __float_as_int(*addr);
    while (__int_as_float(old) < val) {
        int assumed = old;
        old = atomicCAS(ai, assumed, __float_as_int(val));
        if (old == assumed) break;
    }
}
__device__ __forceinline__ void split_bf16(float v, __nv_bfloat16& h, __nv_bfloat16& l) {
    h = __float2bfloat16_rn(v);
    l = __float2bfloat16_rn(v - __bfloat162float(h));
}
__device__ __forceinline__ void split2pack(float a, float b, uint32_t& hi, uint32_t& lo) {
    __nv_bfloat16 ha = __float2bfloat16_rn(a);
    __nv_bfloat16 hb = __float2bfloat16_rn(b);
    __nv_bfloat16 la = __float2bfloat16_rn(a - __bfloat162float(ha));
    __nv_bfloat16 lb = __float2bfloat16_rn(b - __bfloat162float(hb));
    hi = (uint32_t)(*(unsigned short*)&ha) | ((uint32_t)(*(unsigned short*)&hb) << 16);
    lo = (uint32_t)(*(unsigned short*)&la) | ((uint32_t)(*(unsigned short*)&lb) << 16);
}

// ---------------------------------------------------------------------------
__global__ void init_k() {
    int i = blockIdx.x * 256 + threadIdx.x;
    if (i < BH*128*33) d_ctxe[i] = 0.0f;
    if (i < BATCH*CHN) d_xsum[i] = 0.0f;
    if (i < BH)        d_kmax[i] = -INFINITY;
}

__global__ __launch_bounds__(256) void conv_w(const float* __restrict__ wq,
                                              const float* __restrict__ wk,
                                              const float* __restrict__ wv) {
    int z = blockIdx.y, o = blockIdx.x, c = threadIdx.x;
    const float* W = (z == 0) ? wq : ((z == 1) ? wk : wv);
    float v = W[o*CHN + c];
    __nv_bfloat16 h, l; split_bf16(v, h, l);
    d_w3h[(z*CHN + o)*CHN + c] = h;
    d_w3l[(z*CHN + o)*CHN + c] = l;
}

__global__ __launch_bounds__(256) void wcomb_k(const float* __restrict__ wo,
                                               const float* __restrict__ bo,
                                               const float* __restrict__ wp,
                                               const float* __restrict__ bp) {
    int o = blockIdx.x, c = threadIdx.x;
    float acc = 0.0f;
    for (int j = 0; j < CHN; j++) acc += wp[o*CHN + j] * wo[j*CHN + c];
    __nv_bfloat16 h, l; split_bf16(acc, h, l);
    d_wch[o*CHN + c] = h;
    d_wcl[o*CHN + c] = l;
    if (c == 0) {
        float bcc = 0.0f;
        for (int j = 0; j < CHN; j++) bcc += wp[o*CHN + j] * bo[j];
        d_bcomb[o] = bcc + bp[o];
    }
}

// ---------------------------------------------------------------------------
// transpose x -> bf16 hi/lo + accumulate xsum[b][c]
// ---------------------------------------------------------------------------
__global__ __launch_bounds__(256) void xt_k(const float* __restrict__ x) {
    __shared__ float ts[32][33];
    int b = blockIdx.z, c0 = blockIdx.y * 32, p0 = blockIdx.x * 32;
    int tid = threadIdx.x;
    int tx = tid & 31, ty = tid >> 5;
    #pragma unroll
    for (int i = 0; i < 4; i++) {
        int c = c0 + ty + i*8;
        ts[ty + i*8][tx] = x[((size_t)(b*CHN + c))*NTOK + p0 + tx];
    }
    __syncthreads();
    {
        int cl = tid >> 3, j0 = (tid & 7)*4;
        float s = ts[cl][j0] + ts[cl][j0+1] + ts[cl][j0+2] + ts[cl][j0+3];
        s += __shfl_xor_sync(0xffffffffu, s, 1);
        s += __shfl_xor_sync(0xffffffffu, s, 2);
        s += __shfl_xor_sync(0xffffffffu, s, 4);
        if ((tid & 7) == 0) atomicAdd(&d_xsum[b*CHN + c0 + cl], s);
    }
    #pragma unroll
    for (int i = 0; i < 4; i++) {
        int p = p0 + ty + i*8;
        float v = ts[tx][ty + i*8];
        size_t gi = (size_t)(b*NTOK + p)*CHN + c0 + tx;
        __nv_bfloat16 h, l; split_bf16(v, h, l);
        d_xth[gi] = h;
        d_xtl[gi] = l;
    }
}

__global__ __launch_bounds__(32) void vsum_k(const float* __restrict__ wv) {
    int bh = blockIdx.x, d = threadIdx.x;
    int b = bh >> 3, hd = bh & 7;
    const float* xs = &d_xsum[b*CHN];
    const float* wr = &wv[(hd*32 + d)*CHN];
    float s = 0.0f;
    for (int c = 0; c < CHN; c++) s += xs[c]*wr[c];
    d_vsum[bh*32 + d] = s;
}

// ---------------------------------------------------------------------------
// QKV GEMM via mma.sync (128x64) + cp.async double buffering (passing)
// ---------------------------------------------------------------------------
__global__ __launch_bounds__(256) void qkv_mms() {
    extern __shared__ char qsm[];
    uint32_t sb = smem_u32(qsm);
    const int BUF = 30720, AHo = 0, ALo = 10240, BHo = 20480, BLo = 25600;

    int z = blockIdx.z;
    const __nv_bfloat16* WH = d_w3h + (size_t)z*CHN*CHN;
    const __nv_bfloat16* WL = d_w3l + (size_t)z*CHN*CHN;
    float* C = (z == 0) ? d_q : ((z == 1) ? d_k : d_v);
    int m0 = blockIdx.x * 128, n0 = blockIdx.y * 64;
    int tid = threadIdx.x, wid = tid >> 5, lane = tid & 31;
    int wm = (wid & 3) * 32, wn = (wid >> 2) * 32;

    float acc[2][4][4];
    #pragma unroll
    for (int mi = 0; mi < 2; mi++)
        #pragma unroll
        for (int ni = 0; ni < 4; ni++)
            #pragma unroll
            for (int q = 0; q < 4; q++) acc[mi][ni][q] = 0.0f;

    int arow = wm + (lane & 15);
    int acol8 = (lane >> 4) * 8;
    int brow = wn + ((lane >> 4) << 3) + (lane & 7);
    int bcol8 = ((lane >> 3) & 1) * 8;

    auto issue_chunk = [&](int ck, int buf) {
        int k0 = ck * 32;
        uint32_t base = sb + buf*BUF;
        #pragma unroll
        for (int j = 0; j < 2; j++) {
            int i = tid + j*256, row = i >> 2, cg = i & 3;
            size_t g = (size_t)(m0 + row)*CHN + k0 + cg*8;
            uint32_t so = (uint32_t)(row*80 + cg*16);
            cp16(base + AHo + so, d_xth + g);
            cp16(base + ALo + so, d_xtl + g);
        }
        {
            int row = tid >> 2, cg = tid & 3;
            size_t g = (size_t)(n0 + row)*CHN + k0 + cg*8;
            uint32_t so = (uint32_t)(row*80 + cg*16);
            cp16(base + BHo + so, WH + g);
            cp16(base + BLo + so, WL + g);
        }
        asm volatile("cp.async.commit_group;" ::: "memory");
    };

    issue_chunk(0, 0);
    for (int ck = 0; ck < 8; ck++) {
        int buf = ck & 1;
        if (ck < 7) {
            issue_chunk(ck + 1, buf ^ 1);
            asm volatile("cp.async.wait_group 1;" ::: "memory");
        } else {
            asm volatile("cp.async.wait_group 0;" ::: "memory");
        }
        __syncthreads();
        uint32_t base = sb + buf*BUF;
        #pragma unroll
        for (int ks = 0; ks < 32; ks += 16) {
            uint32_t ah[2][4], al[2][4], bh[2][4], bl[2][4];
            #pragma unroll
            for (int mi = 0; mi < 2; mi++) {
                uint32_t aa = base + AHo + (uint32_t)((arow + mi*16)*80 + (ks + acol8)*2);
                ldsm_x4(ah[mi], aa);
                ldsm_x4(al[mi], aa + (ALo - AHo));
            }
            #pragma unroll
            for (int p = 0; p < 2; p++) {
                uint32_t ba = base + BHo + (uint32_t)((brow + p*16)*80 + (ks + bcol8)*2);
                ldsm_x4(bh[p], ba);
                ldsm_x4(bl[p], ba + (BLo - BHo));
            }
            #pragma unroll
            for (int mi = 0; mi < 2; mi++)
                #pragma unroll
                for (int ni = 0; ni < 4; ni++) {
                    const uint32_t* bhp = &bh[ni >> 1][(ni & 1)*2];
                    const uint32_t* blp = &bl[ni >> 1][(ni & 1)*2];
                    mma16816(acc[mi][ni], ah[mi], bhp);
                    mma16816(acc[mi][ni], ah[mi], blp);
                    mma16816(acc[mi][ni], al[mi], bhp);
                }
        }
        __syncthreads();
    }
    #pragma unroll
    for (int mi = 0; mi < 2; mi++)
        #pragma unroll
        for (int ni = 0; ni < 4; ni++) {
            int m = m0 + wm + mi*16 + (lane >> 2);
            int n = n0 + wn + ni*8 + 2*(lane & 3);
            *(float2*)&C[(size_t)m*CHN + n]     = make_float2(acc[mi][ni][0], acc[mi][ni][1]);
            *(float2*)&C[(size_t)(m+8)*CHN + n] = make_float2(acc[mi][ni][2], acc[mi][ni][3]);
        }
}

// ---------------------------------------------------------------------------
// k path via mma.sync. smem aliased: K tile lives inside E region.
// ---------------------------------------------------------------------------
__global__ __launch_bounds__(256, 2) void k_mms(const float* __restrict__ proj) {
    extern __shared__ char sm[];
    const int PH=0, PL=10240, VH=20480, VL=30720,
              EH=40960, EL=75776,           // E: [40960, 110592)
              KH=40960, KL=51200,           // K aliased inside E
              DG=110592, RED=111104;
    uint32_t sb = smem_u32(sm);
    int bh = blockIdx.y, chunk = blockIdx.x;
    int b = bh >> 3, hd = bh & 7;
    int tid = threadIdx.x, wid = tid >> 5, lane = tid & 31;
    int lrow = tid >> 1, lhalf = tid & 1;
    int wtok = wid * 16, wf = wid * 16;

    {
        const float4* p4 = (const float4*)(proj + lrow*32 + lhalf*16);
        #pragma unroll
        for (int i = 0; i < 4; i++) {
            float4 f = p4[i];
            uint32_t h0, l0, h1, l1;
            split2pack(f.x, f.y, h0, l0);
            split2pack(f.z, f.w, h1, l1);
            int co = lrow*80 + lhalf*32 + i*8;
            *(uint2*)(sm + PH + co) = make_uint2(h0, h1);
            *(uint2*)(sm + PL + co) = make_uint2(l0, l1);
        }
    }

    float lmax = -INFINITY;
    float acc2[5][4];
    #pragma unroll
    for (int i = 0; i < 5; i++)
        #pragma unroll
        for (int j = 0; j < 4; j++) acc2[i][j] = 0.0f;

    for (int tile = 0; tile < 9; tile++) {
        int p0 = chunk*1152 + tile*128;
        {
            size_t g = ((size_t)(b*NTOK + p0 + lrow))*CHN + hd*32 + lhalf*16;
            const float4* k4 = (const float4*)(d_k + g);
            const float4* v4 = (const float4*)(d_v + g);
            float sq = 0.0f;
            #pragma unroll
            for (int i = 0; i < 4; i++) {
                float4 kf = k4[i];
                sq += kf.x*kf.x + kf.y*kf.y + kf.z*kf.z + kf.w*kf.w;
                uint32_t h0, l0, h1, l1;
                split2pack(kf.x, kf.y, h0, l0); split2pack(kf.z, kf.w, h1, l1);
                int co = lrow*80 + lhalf*32 + i*8;
                *(uint2*)(sm + KH + co) = make_uint2(h0, h1);
                *(uint2*)(sm + KL + co) = make_uint2(l0, l1);
                float4 vf = v4[i];
                split2pack(vf.x, vf.y, h0, l0); split2pack(vf.z, vf.w, h1, l1);
                *(uint2*)(sm + VH + co) = make_uint2(h0, h1);
                *(uint2*)(sm + VL + co) = make_uint2(l0, l1);
            }
            sq += __shfl_xor_sync(0xffffffffu, sq, 1);
            if (lhalf == 0) {
                ((float*)(sm + DG))[lrow] = sq * HALF_DN2;
            } else {
                *(uint4*)(sm + VH + lrow*80 + 64) = make_uint4(0x00003F80u, 0u, 0u, 0u);
                *(uint4*)(sm + VL + lrow*80 + 64) = make_uint4(0u, 0u, 0u, 0u);
            }
        }
        __syncthreads();

        float acc1[16][4];
        #pragma unroll
        for (int i = 0; i < 16; i++)
            #pragma unroll
            for (int j = 0; j < 4; j++) acc1[i][j] = 0.0f;
        #pragma unroll
        for (int ks = 0; ks < 32; ks += 16) {
            uint32_t ah[4], al[4];
            uint32_t aa = sb + KH + (wtok + (lane & 15))*80 + (ks + ((lane >> 4) << 3))*2;
            ldsm_x4(ah, aa);
            ldsm_x4(al, aa + (KL - KH));
            #pragma unroll
            for (int g = 0; g < 8; g++) {
                uint32_t bhf[4], blf[4];
                uint32_t ba = sb + PH + (g*16 + ((lane >> 4) << 3) + (lane & 7))*80
                                      + (ks + (((lane >> 3) & 1) << 3))*2;
                ldsm_x4(bhf, ba);
                ldsm_x4(blf, ba + (PL - PH));
                #pragma unroll
                for (int h = 0; h < 2; h++) {
                    float* c = acc1[g*2 + h];
                    mma16816(c, ah, &bhf[h*2]);
                    mma16816(c, ah, &blf[h*2]);
                    mma16816(c, al, &bhf[h*2]);
                }
            }
        }
        __syncthreads();   // all warps done reading K before E overwrites it
        {
            int r0 = wtok + (lane >> 2), cq = 2*(lane & 3);
            float dg0 = ((float*)(sm + DG))[r0];
            float dg1 = ((float*)(sm + DG))[r0 + 8];
            #pragma unroll
            for (int f = 0; f < 16; f++) {
                int c0 = f*8 + cq;
                float v0 = acc1[f][0]*DN, v1 = acc1[f][1]*DN;
                float v2 = acc1[f][2]*DN, v3 = acc1[f][3]*DN;
                lmax = fmaxf(lmax, fmaxf(fmaxf(v0, v1), fmaxf(v2, v3)));
                uint32_t h0, l0, h1, l1;
                split2pack(__expf(v0 - dg0), __expf(v1 - dg0), h0, l0);
                split2pack(__expf(v2 - dg1), __expf(v3 - dg1), h1, l1);
                *(uint32_t*)(sm + EH + r0*272 + c0*2)       = h0;
                *(uint32_t*)(sm + EL + r0*272 + c0*2)       = l0;
                *(uint32_t*)(sm + EH + (r0 + 8)*272 + c0*2) = h1;
                *(uint32_t*)(sm + EL + (r0 + 8)*272 + c0*2) = l1;
            }
        }
        __syncthreads();

        #pragma unroll
        for (int kk = 0; kk < 8; kk++) {
            int tok0 = kk*16;
            uint32_t eh[4], el[4];
            uint32_t aa = sb + EH + (tok0 + ((lane >> 4) << 3) + (lane & 7))*272
                                  + (wf + (((lane >> 3) & 1) << 3))*2;
            ldsm_x4_t(eh, aa);
            ldsm_x4_t(el, aa + (EL - EH));
            uint32_t vrowb = sb + VH + (tok0 + (((lane >> 3) & 1) << 3) + (lane & 7))*80;
            uint32_t doff = ((lane >> 4) << 3)*2;
            uint32_t vh0[4], vl0[4], vh1[4], vl1[4], v2h[2], v2l[2];
            ldsm_x4_t(vh0, vrowb + doff);
            ldsm_x4_t(vl0, vrowb + (VL - VH) + doff);
            ldsm_x4_t(vh1, vrowb + 32 + doff);
            ldsm_x4_t(vl1, vrowb + (VL - VH) + 32 + doff);
            ldsm_x2_t(v2h, vrowb + 64);
            ldsm_x2_t(v2l, vrowb + (VL - VH) + 64);
            const uint32_t* bhf[5] = {&vh0[0], &vh0[2], &vh1[0], &vh1[2], &v2h[0]};
            const uint32_t* blf[5] = {&vl0[0], &vl0[2], &vl1[0], &vl1[2], &v2l[0]};
            #pragma unroll
            for (int nf = 0; nf < 5; nf++) {
                mma16816(acc2[nf], eh, bhf[nf]);
                mma16816(acc2[nf], eh, blf[nf]);
                mma16816(acc2[nf], el, bhf[nf]);
            }
        }
        __syncthreads();
    }

    #pragma unroll
    for (int off = 16; off > 0; off >>= 1)
        lmax = fmaxf(lmax, __shfl_xor_sync(0xffffffffu, lmax, off));
    if (lane == 0) ((float*)(sm + RED))[wid] = lmax;
    __syncthreads();
    if (tid == 0) {
        float m = ((float*)(sm + RED))[0];
        #pragma unroll
        for (int i = 1; i < 8; i++) m = fmaxf(m, ((float*)(sm + RED))[i]);
        atomicMaxFloat(&d_kmax[bh], m);
    }
    {
        int r0 = wf + (lane >> 2), cq = 2*(lane & 3);
        #pragma unroll
        for (int nf = 0; nf < 4; nf++) {
            int c0 = nf*8 + cq;
            float* pa = &d_ctxe[((size_t)bh*128 + r0)*33 + c0];
            float* pb = &d_ctxe[((size_t)bh*128 + r0 + 8)*33 + c0];
            atomicAdd(pa,     acc2[nf][0]); atomicAdd(pa + 1, acc2[nf][1]);
            atomicAdd(pb,     acc2[nf][2]); atomicAdd(pb + 1, acc2[nf][3]);
        }
        if ((lane & 3) == 0) {
            atomicAdd(&d_ctxe[((size_t)bh*128 + r0)*33 + 32],     acc2[4][0]);
            atomicAdd(&d_ctxe[((size_t)bh*128 + r0 + 8)*33 + 32], acc2[4][2]);
        }
    }
}

// ---------------------------------------------------------------------------
// finalize -> transposed augmented ctxT bf16 hi/lo
// ---------------------------------------------------------------------------
__global__ __launch_bounds__(128) void k_final() {
    int bh = blockIdx.x, t = threadIdx.x;  // t = feat
    float scale = __expf(-d_kmax[bh]);
    const float* ce = &d_ctxe[((size_t)bh*128 + t)*33];
    size_t tb = (size_t)bh*40*128 + t;
    #pragma unroll
    for (int d = 0; d < 32; d++) {
        float cf = RATIO * (scale * ce[d] + FEPS * d_vsum[bh*DH + d]);
        __nv_bfloat16 h, l; split_bf16(cf, h, l);
        d_ctxTh[tb + d*128] = h;
        d_ctxTl[tb + d*128] = l;
    }
    {
        float ks = RATIO * (scale * ce[32] + FEPS * (float)NTOK);
        __nv_bfloat16 h, l; split_bf16(ks, h, l);
        d_ctxTh[tb + 32*128] = h;
        d_ctxTl[tb + 32*128] = l;
    }
    __nv_bfloat16 z = __float2bfloat16_rn(0.0f);
    #pragma unroll
    for (int d = 33; d < 40; d++) {
        d_ctxTh[tb + d*128] = z;
        d_ctxTl[tb + d*128] = z;
    }
}

// ---------------------------------------------------------------------------
// q path via mma.sync. smem aliased: Q tile inside E region.
// ---------------------------------------------------------------------------
__global__ __launch_bounds__(256, 2) void q_mms(const float* __restrict__ proj) {
    extern __shared__ char sm[];
    const int PH=0, PL=10240, CTH=20480, CTL=31360,
              EH=42240, EL=77056,          // E: [42240, 111872)
              QH=42240, QL=52480,          // Q aliased inside E
              DG=111872;
    uint32_t sb = smem_u32(sm);
    int bh = blockIdx.y, chunk = blockIdx.x;
    int b = bh >> 3, hd = bh & 7;
    int tid = threadIdx.x, wid = tid >> 5, lane = tid & 31;
    int lrow = tid >> 1, lhalf = tid & 1;
    int wtok = wid * 16;

    // proj -> smem
    {
        const float4* p4 = (const float4*)(proj + lrow*32 + lhalf*16);
        #pragma unroll
        for (int i = 0; i < 4; i++) {
            float4 f = p4[i];
            uint32_t h0, l0, h1, l1;
            split2pack(f.x, f.y, h0, l0);
            split2pack(f.z, f.w, h1, l1);
            int co = lrow*80 + lhalf*32 + i*8;
            *(uint2*)(sm + PH + co) = make_uint2(h0, h1);
            *(uint2*)(sm + PL + co) = make_uint2(l0, l1);
        }
    }
    // ctxT -> smem (40 rows x 128 cols = 16 uint4 groups per row, stride 272B)
    {
        const uint4* gh = (const uint4*)(d_ctxTh + (size_t)bh*40*128);
        const uint4* gl = (const uint4*)(d_ctxTl + (size_t)bh*40*128);
        #pragma unroll
        for (int j = 0; j < 3; j++) {
            int idx = tid + j*256;
            if (idx < 640) {
                int row = idx >> 4, cg = idx & 15;
                *(uint4*)(sm + CTH + row*272 + cg*16) = gh[idx];
                *(uint4*)(sm + CTL + row*272 + cg*16) = gl[idx];
            }
        }
    }

    for (int tile = 0; tile < 4; tile++) {
        int p0 = chunk*512 + tile*128;
        // load q tile + diag
        {
            size_t g = ((size_t)(b*NTOK + p0 + lrow))*CHN + hd*32 + lhalf*16;
            const float4* q4 = (const float4*)(d_q + g);
            float sq = 0.0f;
            #pragma unroll
            for (int i = 0; i < 4; i++) {
                float4 qf = q4[i];
                sq += qf.x*qf.x + qf.y*qf.y + qf.z*qf.z + qf.w*qf.w;
                uint32_t h0, l0, h1, l1;
                split2pack(qf.x, qf.y, h0, l0); split2pack(qf.z, qf.w, h1, l1);
                int co = lrow*80 + lhalf*32 + i*8;
                *(uint2*)(sm + QH + co) = make_uint2(h0, h1);
                *(uint2*)(sm + QL + co) = make_uint2(l0, l1);
            }
            sq += __shfl_xor_sync(0xffffffffu, sq, 1);
            if (lhalf == 0) ((float*)(sm + DG))[lrow] = sq * HALF_DN2;
        }
        __syncthreads();

        // MMA1: dash = q . projT
        float acc1[16][4];
        #pragma unroll
        for (int i = 0; i < 16; i++)
            #pragma unroll
            for (int j = 0; j < 4; j++) acc1[i][j] = 0.0f;
        #pragma unroll
        for (int ks = 0; ks < 32; ks += 16) {
            uint32_t ah[4], al[4];
            uint32_t aa = sb + QH + (wtok + (lane & 15))*80 + (ks + ((lane >> 4) << 3))*2;
            ldsm_x4(ah, aa);
            ldsm_x4(al, aa + (QL - QH));
            #pragma unroll
            for (int g = 0; g < 8; g++) {
                uint32_t bhf[4], blf[4];
                uint32_t ba = sb + PH + (g*16 + ((lane >> 4) << 3) + (lane & 7))*80
                                      + (ks + (((lane >> 3) & 1) << 3))*2;
                ldsm_x4(bhf, ba);
                ldsm_x4(blf, ba + (PL - PH));
                #pragma unroll
                for (int h = 0; h < 2; h++) {
                    float* c = acc1[g*2 + h];
                    mma16816(c, ah, &bhf[h*2]);
                    mma16816(c, ah, &blf[h*2]);
                    mma16816(c, al, &bhf[h*2]);
                }
            }
        }
        __syncthreads();   // all warps done reading Q before E overwrites it
        // epilogue 1: per-token max, qp = ratio*(exp(...)+eps)
        {
            int r0 = wtok + (lane >> 2);
            float dg0 = ((float*)(sm + DG))[r0];
            float dg1 = ((float*)(sm + DG))[r0 + 8];
            float mx0 = -INFINITY, mx1 = -INFINITY;
            #pragma unroll
            for (int f = 0; f < 16; f++) {
                mx0 = fmaxf(mx0, fmaxf(acc1[f][0], acc1[f][1]));
                mx1 = fmaxf(mx1, fmaxf(acc1[f][2], acc1[f][3]));
            }
            mx0 = fmaxf(mx0, __shfl_xor_sync(0xffffffffu, mx0, 1));
            mx0 = fmaxf(mx0, __shfl_xor_sync(0xffffffffu, mx0, 2));
            mx1 = fmaxf(mx1, __shfl_xor_sync(0xffffffffu, mx1, 1));
            mx1 = fmaxf(mx1, __shfl_xor_sync(0xffffffffu, mx1, 2));
            mx0 = mx0*DN + dg0;
            mx1 = mx1*DN + dg1;
            int cq = 2*(lane & 3);
            #pragma unroll
            for (int f = 0; f < 16; f++) {
                int c0 = f*8 + cq;
                float e0 = RATIO*(__expf(acc1[f][0]*DN - mx0) + FEPS);
                float e1 = RATIO*(__expf(acc1[f][1]*DN - mx0) + FEPS);
                float e2 = RATIO*(__expf(acc1[f][2]*DN - mx1) + FEPS);
                float e3 = RATIO*(__expf(acc1[f][3]*DN - mx1) + FEPS);
                uint32_t h0, l0, h1, l1;
                split2pack(e0, e1, h0, l0);
                split2pack(e2, e3, h1, l1);
                *(uint32_t*)(sm + EH + r0*272 + c0*2)       = h0;
                *(uint32_t*)(sm + EL + r0*272 + c0*2)       = l0;
                *(uint32_t*)(sm + EH + (r0 + 8)*272 + c0*2) = h1;
                *(uint32_t*)(sm + EL + (r0 + 8)*272 + c0*2) = l1;
            }
        }
        __syncthreads();

        // MMA2: out[16tok][40] = qp . ctxT_aug
        float acc2[5][4];
        #pragma unroll
        for (int i = 0; i < 5; i++)
            #pragma unroll
            for (int j = 0; j < 4; j++) acc2[i][j] = 0.0f;
        #pragma unroll
        for (int ks = 0; ks < 128; ks += 16) {
            uint32_t eh[4], el[4];
            uint32_t aa = sb + EH + (wtok + (lane & 15))*272 + (ks + ((lane >> 4) << 3))*2;
            ldsm_x4(eh, aa);
            ldsm_x4(el, aa + (EL - EH));
            uint32_t b0 = sb + CTH + (((lane >> 4) << 3) + (lane & 7))*272
                                   + (ks + (((lane >> 3) & 1) << 3))*2;
            uint32_t c0h[4], c0l[4], c1h[4], c1l[4], c2h[2], c2l[2];
            ldsm_x4(c0h, b0);
            ldsm_x4(c0l, b0 + (CTL - CTH));
            ldsm_x4(c1h, b0 + 16*272);
            ldsm_x4(c1l, b0 + (CTL - CTH) + 16*272);
            {
                uint32_t b2 = sb + CTH + (32 + (lane & 7))*272
                                       + (ks + (((lane >> 3) & 1) << 3))*2;
                ldsm_x2(c2h, b2);
                ldsm_x2(c2l, b2 + (CTL - CTH));
            }
            const uint32_t* bhf[5] = {&c0h[0], &c0h[2], &c1h[0], &c1h[2], &c2h[0]};
            const uint32_t* blf[5] = {&c0l[0], &c0l[2], &c1l[0], &c1l[2], &c2l[0]};
            #pragma unroll
            for (int nf = 0; nf < 5; nf++) {
                mma16816(acc2[nf], eh, bhf[nf]);
                mma16816(acc2[nf], eh, blf[nf]);
                mma16816(acc2[nf], el, bhf[nf]);
            }
        }
        // epilogue 2: dinv from col 32, write attn bf16 hi/lo
        {
            int r0 = wtok + (lane >> 2), cq = 2*(lane & 3);
            int src = lane & ~3;
            float den0 = __shfl_sync(0xffffffffu, acc2[4][0], src);
            float den1 = __shfl_sync(0xffffffffu, acc2[4][2], src);
            float di0 = 1.0f / den0, di1 = 1.0f / den1;
            size_t g0 = (size_t)(b*NTOK + p0 + r0)*CHN + hd*32;
            size_t g1 = g0 + (size_t)8*CHN;
            #pragma unroll
            for (int nf = 0; nf < 4; nf++) {
                int c0 = nf*8 + cq;
                uint32_t h0, l0, h1, l1;
                split2pack(acc2[nf][0]*di0, acc2[nf][1]*di0, h0, l0);
                split2pack(acc2[nf][2]*di1, acc2[nf][3]*di1, h1, l1);
                *(uint32_t*)(d_ath + g0 + c0) = h0;
                *(uint32_t*)(d_atl + g0 + c0) = l0;
                *(uint32_t*)(d_ath + g1 + c0) = h1;
                *(uint32_t*)(d_atl + g1 + c0) = l1;
            }
        }
        __syncthreads();
    }
}

// ---------------------------------------------------------------------------
// output GEMM via mma.sync + cp.async double buffering; Ct overlays buffers.
// ---------------------------------------------------------------------------
__global__ __launch_bounds__(256) void out_mms(float* __restrict__ out) {
    extern __shared__ char osm[];
    uint32_t sb = smem_u32(osm);
    const int BUF = 30720, AHo = 0, ALo = 10240, BHo = 20480, BLo = 25600;
    float (*Ct)[132] = (float(*)[132])osm;

    int m0 = blockIdx.x * 128, n0 = blockIdx.y * 64;
    int tid = threadIdx.x, wid = tid >> 5, lane = tid & 31;
    int wm = (wid & 3) * 32, wn = (wid >> 2) * 32;

    float acc[2][4][4];
    #pragma unroll
    for (int mi = 0; mi < 2; mi++)
        #pragma unroll
        for (int ni = 0; ni < 4; ni++)
            #pragma unroll
            for (int q = 0; q < 4; q++) acc[mi][ni][q] = 0.0f;

    int arow = wm + (lane & 15);
    int acol8 = (lane >> 4) * 8;
    int brow = wn + ((lane >> 4) << 3) + (lane & 7);
    int bcol8 = ((lane >> 3) & 1) * 8;

    auto issue_chunk = [&](int ck, int buf) {
        int k0 = ck * 32;
        uint32_t base = sb + buf*BUF;
        #pragma unroll
        for (int j = 0; j < 2; j++) {
            int i = tid + j*256, row = i >> 2, cg = i & 3;
            size_t g = (size_t)(m0 + row)*CHN + k0 + cg*8;
            uint32_t so = (uint32_t)(row*80 + cg*16);
            cp16(base + AHo + so, d_ath + g);
            cp16(base + ALo + so, d_atl + g);
        }
        {
            int row = tid >> 2, cg = tid & 3;
            size_t g = (size_t)(n0 + row)*CHN + k0 + cg*8;
            uint32_t so = (uint32_t)(row*80 + cg*16);
            cp16(base + BHo + so, d_wch + g);
            cp16(base + BLo + so, d_wcl + g);
        }
        asm volatile("cp.async.commit_group;" ::: "memory");
    };

    issue_chunk(0, 0);
    for (int ck = 0; ck < 8; ck++) {
        int buf = ck & 1;
        if (ck < 7) {
            issue_chunk(ck + 1, buf ^ 1);
            asm volatile("cp.async.wait_group 1;" ::: "memory");
        } else {
            asm volatile("cp.async.wait_group 0;" ::: "memory");
        }
        __syncthreads();
        uint32_t base = sb + buf*BUF;
        #pragma unroll
        for (int ks = 0; ks < 32; ks += 16) {
            uint32_t ah[2][4], al[2][4], bh[2][4], bl[2][4];
            #pragma unroll
            for (int mi = 0; mi < 2; mi++) {
                uint32_t aa = base + AHo + (uint32_t)((arow + mi*16)*80 + (ks + acol8)*2);
                ldsm_x4(ah[mi], aa);
                ldsm_x4(al[mi], aa + (ALo - AHo));
            }
            #pragma unroll
            for (int p = 0; p < 2; p++) {
                uint32_t ba = base + BHo + (uint32_t)((brow + p*16)*80 + (ks + bcol8)*2);
                ldsm_x4(bh[p], ba);
                ldsm_x4(bl[p], ba + (BLo - BHo));
            }
            #pragma unroll
            for (int mi = 0; mi < 2; mi++)
                #pragma unroll
                for (int ni = 0; ni < 4; ni++) {
                    const uint32_t* bhp = &bh[ni >> 1][(ni & 1)*2];
                    const uint32_t* blp = &bl[ni >> 1][(ni & 1)*2];
                    mma16816(acc[mi][ni], ah[mi], bhp);
                    mma16816(acc[mi][ni], ah[mi], blp);
                    mma16816(acc[mi][ni], al[mi], bhp);
                }
        }
        __syncthreads();
    }

    // stage transposed: Ct[ch_local][tok_local] (overlays cp.async buffers)
    #pragma unroll
    for (int mi = 0; mi < 2; mi++)
        #pragma unroll
        for (int ni = 0; ni < 4; ni++) {
            int ml = wm + mi*16 + (lane >> 2);
            int nl = wn + ni*8 + 2*(lane & 3);
            Ct[nl][ml]       = acc[mi][ni][0];
            Ct[nl+1][ml]     = acc[mi][ni][1];
            Ct[nl][ml+8]     = acc[mi][ni][2];
            Ct[nl+1][ml+8]   = acc[mi][ni][3];
        }
    __syncthreads();

    int bb = m0 / NTOK, ptok = m0 % NTOK;
    int ch = tid >> 2, tg = tid & 3;
    float bias = d_bcomb[n0 + ch];
    size_t rowb = (size_t)(bb*CHN + n0 + ch) * NTOK + ptok;
    #pragma unroll
    for (int j = 0; j < 8; j++) {
        int tl = tg*32 + j*4;
        float4 v = *(float4*)&Ct[ch][tl];
        *(float4*)&out[rowb + tl] = make_float4(v.x+bias, v.y+bias, v.z+bias, v.w+bias);
    }
}

extern "C" void kernel_launch(void* const* d_in, const int* in_sizes, int n_in,
                              void* d_out, int out_size) {
    const float* x    = (const float*)d_in[0];
    const float* wq   = (const float*)d_in[1];
    const float* wk   = (const float*)d_in[2];
    const float* wv   = (const float*)d_in[3];
    const float* wo   = (const float*)d_in[4];
    const float* bo   = (const float*)d_in[5];
    const float* proj = (const float*)d_in[6];
    const float* wp   = (const float*)d_in[7];
    const float* bp   = (const float*)d_in[8];
    float* out = (float*)d_out;

    cudaFuncSetAttribute(qkv_mms, cudaFuncAttributeMaxDynamicSharedMemorySize, 61440);
    cudaFuncSetAttribute(out_mms, cudaFuncAttributeMaxDynamicSharedMemorySize, 61440);
    cudaFuncSetAttribute(k_mms, cudaFuncAttributeMaxDynamicSharedMemorySize, 111616);
    cudaFuncSetAttribute(q_mms, cudaFuncAttributeMaxDynamicSharedMemorySize, 112640);

    init_k<<<768, 256>>>();
    conv_w<<<dim3(256, 3), 256>>>(wq, wk, wv);
    wcomb_k<<<256, 256>>>(wo, bo, wp, bp);
    xt_k<<<dim3(288, 8, 4), 256>>>(x);
    vsum_k<<<BH, 32>>>(wv);
    qkv_mms<<<dim3(288, 4, 3), 256, 61440>>>();
    k_mms<<<dim3(8, BH), 256, 111616>>>(proj);
    k_final<<<BH, 128>>>();
    q_mms<<<dim3(18, BH), 256, 112640>>>(proj);
    out_mms<<<dim3(288, 4), 256, 61440>>>(out);
}

// round 16
// speedup vs baseline: 1.2447x; 1.0724x over previous
#include <cuda_runtime.h>
#include <cuda_bf16.h>
#include <math.h>
#include <cstdint>

#define NTOK 9216
#define BATCH 4
#define CHN 256
#define HEADS 8
#define DH 32
#define NB 128
#define BH (BATCH*HEADS)
#define MTOT (BATCH*NTOK)

#define DN 0.4204482076268573f
#define HALF_DN2 0.08838834764831845f
#define RATIO 0.08838834764831845f
#define FEPS 1e-4f

static __device__ float d_q[MTOT*CHN];
static __device__ float d_k[MTOT*CHN];
static __device__ float d_v[MTOT*CHN];
static __device__ float d_ctxe[(size_t)BH*128*33];  // [bh][feat][0..31=ctx, 32=ksum]
static __device__ float d_vsum[BH*DH];
static __device__ float d_xsum[BATCH*CHN];
static __device__ float d_kmax[BH];
static __device__ float d_bcomb[CHN];

static __device__ __nv_bfloat16 d_xth[(size_t)MTOT*CHN];
static __device__ __nv_bfloat16 d_xtl[(size_t)MTOT*CHN];
static __device__ __nv_bfloat16 d_w3h[3*CHN*CHN];
static __device__ __nv_bfloat16 d_w3l[3*CHN*CHN];
static __device__ __nv_bfloat16 d_ath[(size_t)MTOT*CHN];
static __device__ __nv_bfloat16 d_atl[(size_t)MTOT*CHN];
static __device__ __nv_bfloat16 d_wch[CHN*CHN];
static __device__ __nv_bfloat16 d_wcl[CHN*CHN];
static __device__ __nv_bfloat16 d_ctxTh[BH*40*128];  // [bh][row 0..31=ctx_d, 32=ksum, 33..39=0][feat]
static __device__ __nv_bfloat16 d_ctxTl[BH*40*128];

// ---- mma helpers ----
__device__ __forceinline__ uint32_t smem_u32(const void* p) {
    uint32_t a;
    asm("{ .reg .u64 t; cvta.to.shared.u64 t, %1; cvt.u32.u64 %0, t; }" : "=r"(a) : "l"(p));
    return a;
}
__device__ __forceinline__ void cp16(uint32_t saddr, const void* gptr) {
    asm volatile("cp.async.cg.shared.global [%0], [%1], 16;" :: "r"(saddr), "l"(gptr) : "memory");
}
__device__ __forceinline__ void ldsm_x4(uint32_t* r, uint32_t addr) {
    asm volatile("ldmatrix.sync.aligned.m8n8.x4.shared.b16 {%0,%1,%2,%3}, [%4];"
        : "=r"(r[0]), "=r"(r[1]), "=r"(r[2]), "=r"(r[3]) : "r"(addr));
}
__device__ __forceinline__ void ldsm_x2(uint32_t* r, uint32_t addr) {
    asm volatile("ldmatrix.sync.aligned.m8n8.x2.shared.b16 {%0,%1}, [%2];"
        : "=r"(r[0]), "=r"(r[1]) : "r"(addr));
}
__device__ __forceinline__ void ldsm_x4_t(uint32_t* r, uint32_t addr) {
    asm volatile("ldmatrix.sync.aligned.m8n8.x4.trans.shared.b16 {%0,%1,%2,%3}, [%4];"
        : "=r"(r[0]), "=r"(r[1]), "=r"(r[2]), "=r"(r[3]) : "r"(addr));
}
__device__ __forceinline__ void ldsm_x2_t(uint32_t* r, uint32_t addr) {
    asm volatile("ldmatrix.sync.aligned.m8n8.x2.trans.shared.b16 {%0,%1}, [%2];"
        : "=r"(r[0]), "=r"(r[1]) : "r"(addr));
}
__device__ __forceinline__ void mma16816(float* c, const uint32_t* a, const uint32_t* b) {
    asm volatile("mma.sync.aligned.m16n8k16.row.col.f32.bf16.bf16.f32 "
        "{%0,%1,%2,%3}, {%4,%5,%6,%7}, {%8,%9}, {%0,%1,%2,%3};"
        : "+f"(c[0]), "+f"(c[1]), "+f"(c[2]), "+f"(c[3])
        : "r"(a[0]), "r"(a[1]), "r"(a[2]), "r"(a[3]), "r"(b[0]), "r"(b[1]));
}
__device__ __forceinline__ void atomicMaxFloat(float* addr, float val) {
    int* ai = (int*)addr;
    int old = __float_as_int(*addr);
    while (__int_as_float(old) < val) {
        int assumed = old;
        old = atomicCAS(ai, assumed, __float_as_int(val));
        if (old == assumed) break;
    }
}
__device__ __forceinline__ void split_bf16(float v, __nv_bfloat16& h, __nv_bfloat16& l) {
    h = __float2bfloat16_rn(v);
    l = __float2bfloat16_rn(v - __bfloat162float(h));
}
__device__ __forceinline__ void split2pack(float a, float b, uint32_t& hi, uint32_t& lo) {
    __nv_bfloat16 ha = __float2bfloat16_rn(a);
    __nv_bfloat16 hb = __float2bfloat16_rn(b);
    __nv_bfloat16 la = __float2bfloat16_rn(a - __bfloat162float(ha));
    __nv_bfloat16 lb = __float2bfloat16_rn(b - __bfloat162float(hb));
    hi = (uint32_t)(*(unsigned short*)&ha) | ((uint32_t)(*(unsigned short*)&hb) << 16);
    lo = (uint32_t)(*(unsigned short*)&la) | ((uint32_t)(*(unsigned short*)&lb) << 16);
}
__device__ __forceinline__ uint32_t pack2hi(float a, float b) {
    __nv_bfloat162 t = __floats2bfloat162_rn(a, b);
    return *(uint32_t*)&t;
}

// ---------------------------------------------------------------------------
__global__ void init_k() {
    int i = blockIdx.x * 256 + threadIdx.x;
    if (i < BH*128*33) d_ctxe[i] = 0.0f;
    if (i < BATCH*CHN) d_xsum[i] = 0.0f;
    if (i < BH)        d_kmax[i] = -INFINITY;
}

__global__ __launch_bounds__(256) void conv_w(const float* __restrict__ wq,
                                              const float* __restrict__ wk,
                                              const float* __restrict__ wv) {
    int z = blockIdx.y, o = blockIdx.x, c = threadIdx.x;
    const float* W = (z == 0) ? wq : ((z == 1) ? wk : wv);
    float v = W[o*CHN + c];
    __nv_bfloat16 h, l; split_bf16(v, h, l);
    d_w3h[(z*CHN + o)*CHN + c] = h;
    d_w3l[(z*CHN + o)*CHN + c] = l;
}

__global__ __launch_bounds__(256) void wcomb_k(const float* __restrict__ wo,
                                               const float* __restrict__ bo,
                                               const float* __restrict__ wp,
                                               const float* __restrict__ bp) {
    int o = blockIdx.x, c = threadIdx.x;
    float acc = 0.0f;
    for (int j = 0; j < CHN; j++) acc += wp[o*CHN + j] * wo[j*CHN + c];
    __nv_bfloat16 h, l; split_bf16(acc, h, l);
    d_wch[o*CHN + c] = h;
    d_wcl[o*CHN + c] = l;
    if (c == 0) {
        float bcc = 0.0f;
        for (int j = 0; j < CHN; j++) bcc += wp[o*CHN + j] * bo[j];
        d_bcomb[o] = bcc + bp[o];
    }
}

// ---------------------------------------------------------------------------
// transpose x -> bf16 hi/lo + accumulate xsum[b][c]
// ---------------------------------------------------------------------------
__global__ __launch_bounds__(256) void xt_k(const float* __restrict__ x) {
    __shared__ float ts[32][33];
    int b = blockIdx.z, c0 = blockIdx.y * 32, p0 = blockIdx.x * 32;
    int tid = threadIdx.x;
    int tx = tid & 31, ty = tid >> 5;
    #pragma unroll
    for (int i = 0; i < 4; i++) {
        int c = c0 + ty + i*8;
        ts[ty + i*8][tx] = x[((size_t)(b*CHN + c))*NTOK + p0 + tx];
    }
    __syncthreads();
    {
        int cl = tid >> 3, j0 = (tid & 7)*4;
        float s = ts[cl][j0] + ts[cl][j0+1] + ts[cl][j0+2] + ts[cl][j0+3];
        s += __shfl_xor_sync(0xffffffffu, s, 1);
        s += __shfl_xor_sync(0xffffffffu, s, 2);
        s += __shfl_xor_sync(0xffffffffu, s, 4);
        if ((tid & 7) == 0) atomicAdd(&d_xsum[b*CHN + c0 + cl], s);
    }
    #pragma unroll
    for (int i = 0; i < 4; i++) {
        int p = p0 + ty + i*8;
        float v = ts[tx][ty + i*8];
        size_t gi = (size_t)(b*NTOK + p)*CHN + c0 + tx;
        __nv_bfloat16 h, l; split_bf16(v, h, l);
        d_xth[gi] = h;
        d_xtl[gi] = l;
    }
}

__global__ __launch_bounds__(32) void vsum_k(const float* __restrict__ wv) {
    int bh = blockIdx.x, d = threadIdx.x;
    int b = bh >> 3, hd = bh & 7;
    const float* xs = &d_xsum[b*CHN];
    const float* wr = &wv[(hd*32 + d)*CHN];
    float s = 0.0f;
    for (int c = 0; c < CHN; c++) s += xs[c]*wr[c];
    d_vsum[bh*32 + d] = s;
}

// ---------------------------------------------------------------------------
// QKV GEMM via mma.sync (128x64) + cp.async double buffering (passing)
// ---------------------------------------------------------------------------
__global__ __launch_bounds__(256) void qkv_mms() {
    extern __shared__ char qsm[];
    uint32_t sb = smem_u32(qsm);
    const int BUF = 30720, AHo = 0, ALo = 10240, BHo = 20480, BLo = 25600;

    int z = blockIdx.z;
    const __nv_bfloat16* WH = d_w3h + (size_t)z*CHN*CHN;
    const __nv_bfloat16* WL = d_w3l + (size_t)z*CHN*CHN;
    float* C = (z == 0) ? d_q : ((z == 1) ? d_k : d_v);
    int m0 = blockIdx.x * 128, n0 = blockIdx.y * 64;
    int tid = threadIdx.x, wid = tid >> 5, lane = tid & 31;
    int wm = (wid & 3) * 32, wn = (wid >> 2) * 32;

    float acc[2][4][4];
    #pragma unroll
    for (int mi = 0; mi < 2; mi++)
        #pragma unroll
        for (int ni = 0; ni < 4; ni++)
            #pragma unroll
            for (int q = 0; q < 4; q++) acc[mi][ni][q] = 0.0f;

    int arow = wm + (lane & 15);
    int acol8 = (lane >> 4) * 8;
    int brow = wn + ((lane >> 4) << 3) + (lane & 7);
    int bcol8 = ((lane >> 3) & 1) * 8;

    auto issue_chunk = [&](int ck, int buf) {
        int k0 = ck * 32;
        uint32_t base = sb + buf*BUF;
        #pragma unroll
        for (int j = 0; j < 2; j++) {
            int i = tid + j*256, row = i >> 2, cg = i & 3;
            size_t g = (size_t)(m0 + row)*CHN + k0 + cg*8;
            uint32_t so = (uint32_t)(row*80 + cg*16);
            cp16(base + AHo + so, d_xth + g);
            cp16(base + ALo + so, d_xtl + g);
        }
        {
            int row = tid >> 2, cg = tid & 3;
            size_t g = (size_t)(n0 + row)*CHN + k0 + cg*8;
            uint32_t so = (uint32_t)(row*80 + cg*16);
            cp16(base + BHo + so, WH + g);
            cp16(base + BLo + so, WL + g);
        }
        asm volatile("cp.async.commit_group;" ::: "memory");
    };

    issue_chunk(0, 0);
    for (int ck = 0; ck < 8; ck++) {
        int buf = ck & 1;
        if (ck < 7) {
            issue_chunk(ck + 1, buf ^ 1);
            asm volatile("cp.async.wait_group 1;" ::: "memory");
        } else {
            asm volatile("cp.async.wait_group 0;" ::: "memory");
        }
        __syncthreads();
        uint32_t base = sb + buf*BUF;
        #pragma unroll
        for (int ks = 0; ks < 32; ks += 16) {
            uint32_t ah[2][4], al[2][4], bh[2][4], bl[2][4];
            #pragma unroll
            for (int mi = 0; mi < 2; mi++) {
                uint32_t aa = base + AHo + (uint32_t)((arow + mi*16)*80 + (ks + acol8)*2);
                ldsm_x4(ah[mi], aa);
                ldsm_x4(al[mi], aa + (ALo - AHo));
            }
            #pragma unroll
            for (int p = 0; p < 2; p++) {
                uint32_t ba = base + BHo + (uint32_t)((brow + p*16)*80 + (ks + bcol8)*2);
                ldsm_x4(bh[p], ba);
                ldsm_x4(bl[p], ba + (BLo - BHo));
            }
            #pragma unroll
            for (int mi = 0; mi < 2; mi++)
                #pragma unroll
                for (int ni = 0; ni < 4; ni++) {
                    const uint32_t* bhp = &bh[ni >> 1][(ni & 1)*2];
                    const uint32_t* blp = &bl[ni >> 1][(ni & 1)*2];
                    mma16816(acc[mi][ni], ah[mi], bhp);
                    mma16816(acc[mi][ni], ah[mi], blp);
                    mma16816(acc[mi][ni], al[mi], bhp);
                }
        }
        __syncthreads();
    }
    #pragma unroll
    for (int mi = 0; mi < 2; mi++)
        #pragma unroll
        for (int ni = 0; ni < 4; ni++) {
            int m = m0 + wm + mi*16 + (lane >> 2);
            int n = n0 + wn + ni*8 + 2*(lane & 3);
            *(float2*)&C[(size_t)m*CHN + n]     = make_float2(acc[mi][ni][0], acc[mi][ni][1]);
            *(float2*)&C[(size_t)(m+8)*CHN + n] = make_float2(acc[mi][ni][2], acc[mi][ni][3]);
        }
}

// ---------------------------------------------------------------------------
// k path via mma.sync. E stored bf16-hi only (lo term dropped: 2^-9 per-term
// error averages to ~1e-5 over 9216 tokens). K aliased inside E region.
// ---------------------------------------------------------------------------
__global__ __launch_bounds__(256, 2) void k_mms(const float* __restrict__ proj) {
    extern __shared__ char sm[];
    const int PH=0, PL=10240, VH=20480, VL=30720,
              EH=40960,                     // E: [40960, 75776)
              KH=40960, KL=51200,           // K aliased inside E
              DG=75776, RED=76288;
    uint32_t sb = smem_u32(sm);
    int bh = blockIdx.y, chunk = blockIdx.x;
    int b = bh >> 3, hd = bh & 7;
    int tid = threadIdx.x, wid = tid >> 5, lane = tid & 31;
    int lrow = tid >> 1, lhalf = tid & 1;
    int wtok = wid * 16, wf = wid * 16;

    {
        const float4* p4 = (const float4*)(proj + lrow*32 + lhalf*16);
        #pragma unroll
        for (int i = 0; i < 4; i++) {
            float4 f = p4[i];
            uint32_t h0, l0, h1, l1;
            split2pack(f.x, f.y, h0, l0);
            split2pack(f.z, f.w, h1, l1);
            int co = lrow*80 + lhalf*32 + i*8;
            *(uint2*)(sm + PH + co) = make_uint2(h0, h1);
            *(uint2*)(sm + PL + co) = make_uint2(l0, l1);
        }
    }

    float lmax = -INFINITY;
    float acc2[5][4];
    #pragma unroll
    for (int i = 0; i < 5; i++)
        #pragma unroll
        for (int j = 0; j < 4; j++) acc2[i][j] = 0.0f;

    for (int tile = 0; tile < 9; tile++) {
        int p0 = chunk*1152 + tile*128;
        {
            size_t g = ((size_t)(b*NTOK + p0 + lrow))*CHN + hd*32 + lhalf*16;
            const float4* k4 = (const float4*)(d_k + g);
            const float4* v4 = (const float4*)(d_v + g);
            float sq = 0.0f;
            #pragma unroll
            for (int i = 0; i < 4; i++) {
                float4 kf = k4[i];
                sq += kf.x*kf.x + kf.y*kf.y + kf.z*kf.z + kf.w*kf.w;
                uint32_t h0, l0, h1, l1;
                split2pack(kf.x, kf.y, h0, l0); split2pack(kf.z, kf.w, h1, l1);
                int co = lrow*80 + lhalf*32 + i*8;
                *(uint2*)(sm + KH + co) = make_uint2(h0, h1);
                *(uint2*)(sm + KL + co) = make_uint2(l0, l1);
                float4 vf = v4[i];
                split2pack(vf.x, vf.y, h0, l0); split2pack(vf.z, vf.w, h1, l1);
                *(uint2*)(sm + VH + co) = make_uint2(h0, h1);
                *(uint2*)(sm + VL + co) = make_uint2(l0, l1);
            }
            sq += __shfl_xor_sync(0xffffffffu, sq, 1);
            if (lhalf == 0) {
                ((float*)(sm + DG))[lrow] = sq * HALF_DN2;
            } else {
                *(uint4*)(sm + VH + lrow*80 + 64) = make_uint4(0x00003F80u, 0u, 0u, 0u);
                *(uint4*)(sm + VL + lrow*80 + 64) = make_uint4(0u, 0u, 0u, 0u);
            }
        }
        __syncthreads();

        float acc1[16][4];
        #pragma unroll
        for (int i = 0; i < 16; i++)
            #pragma unroll
            for (int j = 0; j < 4; j++) acc1[i][j] = 0.0f;
        #pragma unroll
        for (int ks = 0; ks < 32; ks += 16) {
            uint32_t ah[4], al[4];
            uint32_t aa = sb + KH + (wtok + (lane & 15))*80 + (ks + ((lane >> 4) << 3))*2;
            ldsm_x4(ah, aa);
            ldsm_x4(al, aa + (KL - KH));
            #pragma unroll
            for (int g = 0; g < 8; g++) {
                uint32_t bhf[4], blf[4];
                uint32_t ba = sb + PH + (g*16 + ((lane >> 4) << 3) + (lane & 7))*80
                                      + (ks + (((lane >> 3) & 1) << 3))*2;
                ldsm_x4(bhf, ba);
                ldsm_x4(blf, ba + (PL - PH));
                #pragma unroll
                for (int h = 0; h < 2; h++) {
                    float* c = acc1[g*2 + h];
                    mma16816(c, ah, &bhf[h*2]);
                    mma16816(c, ah, &blf[h*2]);
                    mma16816(c, al, &bhf[h*2]);
                }
            }
        }
        __syncthreads();   // all warps done reading K before E overwrites it
        {
            int r0 = wtok + (lane >> 2), cq = 2*(lane & 3);
            float dg0 = ((float*)(sm + DG))[r0];
            float dg1 = ((float*)(sm + DG))[r0 + 8];
            #pragma unroll
            for (int f = 0; f < 16; f++) {
                int c0 = f*8 + cq;
                float v0 = acc1[f][0]*DN, v1 = acc1[f][1]*DN;
                float v2 = acc1[f][2]*DN, v3 = acc1[f][3]*DN;
                lmax = fmaxf(lmax, fmaxf(fmaxf(v0, v1), fmaxf(v2, v3)));
                *(uint32_t*)(sm + EH + r0*272 + c0*2)       = pack2hi(__expf(v0 - dg0), __expf(v1 - dg0));
                *(uint32_t*)(sm + EH + (r0 + 8)*272 + c0*2) = pack2hi(__expf(v2 - dg1), __expf(v3 - dg1));
            }
        }
        __syncthreads();

        #pragma unroll
        for (int kk = 0; kk < 8; kk++) {
            int tok0 = kk*16;
            uint32_t eh[4];
            uint32_t aa = sb + EH + (tok0 + ((lane >> 4) << 3) + (lane & 7))*272
                                  + (wf + (((lane >> 3) & 1) << 3))*2;
            ldsm_x4_t(eh, aa);
            uint32_t vrowb = sb + VH + (tok0 + (((lane >> 3) & 1) << 3) + (lane & 7))*80;
            uint32_t doff = ((lane >> 4) << 3)*2;
            uint32_t vh0[4], vl0[4], vh1[4], vl1[4], v2h[2], v2l[2];
            ldsm_x4_t(vh0, vrowb + doff);
            ldsm_x4_t(vl0, vrowb + (VL - VH) + doff);
            ldsm_x4_t(vh1, vrowb + 32 + doff);
            ldsm_x4_t(vl1, vrowb + (VL - VH) + 32 + doff);
            ldsm_x2_t(v2h, vrowb + 64);
            ldsm_x2_t(v2l, vrowb + (VL - VH) + 64);
            const uint32_t* bhf[5] = {&vh0[0], &vh0[2], &vh1[0], &vh1[2], &v2h[0]};
            const uint32_t* blf[5] = {&vl0[0], &vl0[2], &vl1[0], &vl1[2], &v2l[0]};
            #pragma unroll
            for (int nf = 0; nf < 5; nf++) {
                mma16816(acc2[nf], eh, bhf[nf]);
                mma16816(acc2[nf], eh, blf[nf]);
            }
        }
        __syncthreads();
    }

    #pragma unroll
    for (int off = 16; off > 0; off >>= 1)
        lmax = fmaxf(lmax, __shfl_xor_sync(0xffffffffu, lmax, off));
    if (lane == 0) ((float*)(sm + RED))[wid] = lmax;
    __syncthreads();
    if (tid == 0) {
        float m = ((float*)(sm + RED))[0];
        #pragma unroll
        for (int i = 1; i < 8; i++) m = fmaxf(m, ((float*)(sm + RED))[i]);
        atomicMaxFloat(&d_kmax[bh], m);
    }
    {
        int r0 = wf + (lane >> 2), cq = 2*(lane & 3);
        #pragma unroll
        for (int nf = 0; nf < 4; nf++) {
            int c0 = nf*8 + cq;
            float* pa = &d_ctxe[((size_t)bh*128 + r0)*33 + c0];
            float* pb = &d_ctxe[((size_t)bh*128 + r0 + 8)*33 + c0];
            atomicAdd(pa,     acc2[nf][0]); atomicAdd(pa + 1, acc2[nf][1]);
            atomicAdd(pb,     acc2[nf][2]); atomicAdd(pb + 1, acc2[nf][3]);
        }
        if ((lane & 3) == 0) {
            atomicAdd(&d_ctxe[((size_t)bh*128 + r0)*33 + 32],     acc2[4][0]);
            atomicAdd(&d_ctxe[((size_t)bh*128 + r0 + 8)*33 + 32], acc2[4][2]);
        }
    }
}

// ---------------------------------------------------------------------------
// finalize -> transposed augmented ctxT bf16 hi/lo
// ---------------------------------------------------------------------------
__global__ __launch_bounds__(128) void k_final() {
    int bh = blockIdx.x, t = threadIdx.x;  // t = feat
    float scale = __expf(-d_kmax[bh]);
    const float* ce = &d_ctxe[((size_t)bh*128 + t)*33];
    size_t tb = (size_t)bh*40*128 + t;
    #pragma unroll
    for (int d = 0; d < 32; d++) {
        float cf = RATIO * (scale * ce[d] + FEPS * d_vsum[bh*DH + d]);
        __nv_bfloat16 h, l; split_bf16(cf, h, l);
        d_ctxTh[tb + d*128] = h;
        d_ctxTl[tb + d*128] = l;
    }
    {
        float ks = RATIO * (scale * ce[32] + FEPS * (float)NTOK);
        __nv_bfloat16 h, l; split_bf16(ks, h, l);
        d_ctxTh[tb + 32*128] = h;
        d_ctxTl[tb + 32*128] = l;
    }
    __nv_bfloat16 z = __float2bfloat16_rn(0.0f);
    #pragma unroll
    for (int d = 33; d < 40; d++) {
        d_ctxTh[tb + d*128] = z;
        d_ctxTl[tb + d*128] = z;
    }
}

// ---------------------------------------------------------------------------
// q path via mma.sync. qp stored bf16-hi only; Q aliased inside E region.
// ---------------------------------------------------------------------------
__global__ __launch_bounds__(256, 2) void q_mms(const float* __restrict__ proj) {
    extern __shared__ char sm[];
    const int PH=0, PL=10240, CTH=20480, CTL=31360,
              EH=42240,                    // E: [42240, 77056)
              QH=42240, QL=52480,          // Q aliased inside E
              DG=77056;
    uint32_t sb = smem_u32(sm);
    int bh = blockIdx.y, chunk = blockIdx.x;
    int b = bh >> 3, hd = bh & 7;
    int tid = threadIdx.x, wid = tid >> 5, lane = tid & 31;
    int lrow = tid >> 1, lhalf = tid & 1;
    int wtok = wid * 16;

    // proj -> smem
    {
        const float4* p4 = (const float4*)(proj + lrow*32 + lhalf*16);
        #pragma unroll
        for (int i = 0; i < 4; i++) {
            float4 f = p4[i];
            uint32_t h0, l0, h1, l1;
            split2pack(f.x, f.y, h0, l0);
            split2pack(f.z, f.w, h1, l1);
            int co = lrow*80 + lhalf*32 + i*8;
            *(uint2*)(sm + PH + co) = make_uint2(h0, h1);
            *(uint2*)(sm + PL + co) = make_uint2(l0, l1);
        }
    }
    // ctxT -> smem (40 rows x 128 cols = 16 uint4 groups per row, stride 272B)
    {
        const uint4* gh = (const uint4*)(d_ctxTh + (size_t)bh*40*128);
        const uint4* gl = (const uint4*)(d_ctxTl + (size_t)bh*40*128);
        #pragma unroll
        for (int j = 0; j < 3; j++) {
            int idx = tid + j*256;
            if (idx < 640) {
                int row = idx >> 4, cg = idx & 15;
                *(uint4*)(sm + CTH + row*272 + cg*16) = gh[idx];
                *(uint4*)(sm + CTL + row*272 + cg*16) = gl[idx];
            }
        }
    }

    for (int tile = 0; tile < 4; tile++) {
        int p0 = chunk*512 + tile*128;
        // load q tile + diag
        {
            size_t g = ((size_t)(b*NTOK + p0 + lrow))*CHN + hd*32 + lhalf*16;
            const float4* q4 = (const float4*)(d_q + g);
            float sq = 0.0f;
            #pragma unroll
            for (int i = 0; i < 4; i++) {
                float4 qf = q4[i];
                sq += qf.x*qf.x + qf.y*qf.y + qf.z*qf.z + qf.w*qf.w;
                uint32_t h0, l0, h1, l1;
                split2pack(qf.x, qf.y, h0, l0); split2pack(qf.z, qf.w, h1, l1);
                int co = lrow*80 + lhalf*32 + i*8;
                *(uint2*)(sm + QH + co) = make_uint2(h0, h1);
                *(uint2*)(sm + QL + co) = make_uint2(l0, l1);
            }
            sq += __shfl_xor_sync(0xffffffffu, sq, 1);
            if (lhalf == 0) ((float*)(sm + DG))[lrow] = sq * HALF_DN2;
        }
        __syncthreads();

        // MMA1: dash = q . projT
        float acc1[16][4];
        #pragma unroll
        for (int i = 0; i < 16; i++)
            #pragma unroll
            for (int j = 0; j < 4; j++) acc1[i][j] = 0.0f;
        #pragma unroll
        for (int ks = 0; ks < 32; ks += 16) {
            uint32_t ah[4], al[4];
            uint32_t aa = sb + QH + (wtok + (lane & 15))*80 + (ks + ((lane >> 4) << 3))*2;
            ldsm_x4(ah, aa);
            ldsm_x4(al, aa + (QL - QH));
            #pragma unroll
            for (int g = 0; g < 8; g++) {
                uint32_t bhf[4], blf[4];
                uint32_t ba = sb + PH + (g*16 + ((lane >> 4) << 3) + (lane & 7))*80
                                      + (ks + (((lane >> 3) & 1) << 3))*2;
                ldsm_x4(bhf, ba);
                ldsm_x4(blf, ba + (PL - PH));
                #pragma unroll
                for (int h = 0; h < 2; h++) {
                    float* c = acc1[g*2 + h];
                    mma16816(c, ah, &bhf[h*2]);
                    mma16816(c, ah, &blf[h*2]);
                    mma16816(c, al, &bhf[h*2]);
                }
            }
        }
        __syncthreads();   // all warps done reading Q before E overwrites it
        // epilogue 1: per-token max, qp = ratio*(exp(...)+eps), bf16-hi only
        {
            int r0 = wtok + (lane >> 2);
            float dg0 = ((float*)(sm + DG))[r0];
            float dg1 = ((float*)(sm + DG))[r0 + 8];
            float mx0 = -INFINITY, mx1 = -INFINITY;
            #pragma unroll
            for (int f = 0; f < 16; f++) {
                mx0 = fmaxf(mx0, fmaxf(acc1[f][0], acc1[f][1]));
                mx1 = fmaxf(mx1, fmaxf(acc1[f][2], acc1[f][3]));
            }
            mx0 = fmaxf(mx0, __shfl_xor_sync(0xffffffffu, mx0, 1));
            mx0 = fmaxf(mx0, __shfl_xor_sync(0xffffffffu, mx0, 2));
            mx1 = fmaxf(mx1, __shfl_xor_sync(0xffffffffu, mx1, 1));
            mx1 = fmaxf(mx1, __shfl_xor_sync(0xffffffffu, mx1, 2));
            mx0 = mx0*DN + dg0;
            mx1 = mx1*DN + dg1;
            int cq = 2*(lane & 3);
            #pragma unroll
            for (int f = 0; f < 16; f++) {
                int c0 = f*8 + cq;
                float e0 = RATIO*(__expf(acc1[f][0]*DN - mx0) + FEPS);
                float e1 = RATIO*(__expf(acc1[f][1]*DN - mx0) + FEPS);
                float e2 = RATIO*(__expf(acc1[f][2]*DN - mx1) + FEPS);
                float e3 = RATIO*(__expf(acc1[f][3]*DN - mx1) + FEPS);
                *(uint32_t*)(sm + EH + r0*272 + c0*2)       = pack2hi(e0, e1);
                *(uint32_t*)(sm + EH + (r0 + 8)*272 + c0*2) = pack2hi(e2, e3);
            }
        }
        __syncthreads();

        // MMA2: out[16tok][40] = qp . ctxT_aug
        float acc2[5][4];
        #pragma unroll
        for (int i = 0; i < 5; i++)
            #pragma unroll
            for (int j = 0; j < 4; j++) acc2[i][j] = 0.0f;
        #pragma unroll
        for (int ks = 0; ks < 128; ks += 16) {
            uint32_t eh[4];
            uint32_t aa = sb + EH + (wtok + (lane & 15))*272 + (ks + ((lane >> 4) << 3))*2;
            ldsm_x4(eh, aa);
            uint32_t b0 = sb + CTH + (((lane >> 4) << 3) + (lane & 7))*272
                                   + (ks + (((lane >> 3) & 1) << 3))*2;
            uint32_t c0h[4], c0l[4], c1h[4], c1l[4], c2h[2], c2l[2];
            ldsm_x4(c0h, b0);
            ldsm_x4(c0l, b0 + (CTL - CTH));
            ldsm_x4(c1h, b0 + 16*272);
            ldsm_x4(c1l, b0 + (CTL - CTH) + 16*272);
            {
                uint32_t b2 = sb + CTH + (32 + (lane & 7))*272
                                       + (ks + (((lane >> 3) & 1) << 3))*2;
                ldsm_x2(c2h, b2);
                ldsm_x2(c2l, b2 + (CTL - CTH));
            }
            const uint32_t* bhf[5] = {&c0h[0], &c0h[2], &c1h[0], &c1h[2], &c2h[0]};
            const uint32_t* blf[5] = {&c0l[0], &c0l[2], &c1l[0], &c1l[2], &c2l[0]};
            #pragma unroll
            for (int nf = 0; nf < 5; nf++) {
                mma16816(acc2[nf], eh, bhf[nf]);
                mma16816(acc2[nf], eh, blf[nf]);
            }
        }
        // epilogue 2: dinv from col 32, write attn bf16 hi/lo
        {
            int r0 = wtok + (lane >> 2), cq = 2*(lane & 3);
            int src = lane & ~3;
            float den0 = __shfl_sync(0xffffffffu, acc2[4][0], src);
            float den1 = __shfl_sync(0xffffffffu, acc2[4][2], src);
            float di0 = 1.0f / den0, di1 = 1.0f / den1;
            size_t g0 = (size_t)(b*NTOK + p0 + r0)*CHN + hd*32;
            size_t g1 = g0 + (size_t)8*CHN;
            #pragma unroll
            for (int nf = 0; nf < 4; nf++) {
                int c0 = nf*8 + cq;
                uint32_t h0, l0, h1, l1;
                split2pack(acc2[nf][0]*di0, acc2[nf][1]*di0, h0, l0);
                split2pack(acc2[nf][2]*di1, acc2[nf][3]*di1, h1, l1);
                *(uint32_t*)(d_ath + g0 + c0) = h0;
                *(uint32_t*)(d_atl + g0 + c0) = l0;
                *(uint32_t*)(d_ath + g1 + c0) = h1;
                *(uint32_t*)(d_atl + g1 + c0) = l1;
            }
        }
        __syncthreads();
    }
}

// ---------------------------------------------------------------------------
// output GEMM via mma.sync + cp.async double buffering; Ct overlays buffers.
// ---------------------------------------------------------------------------
__global__ __launch_bounds__(256) void out_mms(float* __restrict__ out) {
    extern __shared__ char osm[];
    uint32_t sb = smem_u32(osm);
    const int BUF = 30720, AHo = 0, ALo = 10240, BHo = 20480, BLo = 25600;
    float (*Ct)[132] = (float(*)[132])osm;

    int m0 = blockIdx.x * 128, n0 = blockIdx.y * 64;
    int tid = threadIdx.x, wid = tid >> 5, lane = tid & 31;
    int wm = (wid & 3) * 32, wn = (wid >> 2) * 32;

    float acc[2][4][4];
    #pragma unroll
    for (int mi = 0; mi < 2; mi++)
        #pragma unroll
        for (int ni = 0; ni < 4; ni++)
            #pragma unroll
            for (int q = 0; q < 4; q++) acc[mi][ni][q] = 0.0f;

    int arow = wm + (lane & 15);
    int acol8 = (lane >> 4) * 8;
    int brow = wn + ((lane >> 4) << 3) + (lane & 7);
    int bcol8 = ((lane >> 3) & 1) * 8;

    auto issue_chunk = [&](int ck, int buf) {
        int k0 = ck * 32;
        uint32_t base = sb + buf*BUF;
        #pragma unroll
        for (int j = 0; j < 2; j++) {
            int i = tid + j*256, row = i >> 2, cg = i & 3;
            size_t g = (size_t)(m0 + row)*CHN + k0 + cg*8;
            uint32_t so = (uint32_t)(row*80 + cg*16);
            cp16(base + AHo + so, d_ath + g);
            cp16(base + ALo + so, d_atl + g);
        }
        {
            int row = tid >> 2, cg = tid & 3;
            size_t g = (size_t)(n0 + row)*CHN + k0 + cg*8;
            uint32_t so = (uint32_t)(row*80 + cg*16);
            cp16(base + BHo + so, d_wch + g);
            cp16(base + BLo + so, d_wcl + g);
        }
        asm volatile("cp.async.commit_group;" ::: "memory");
    };

    issue_chunk(0, 0);
    for (int ck = 0; ck < 8; ck++) {
        int buf = ck & 1;
        if (ck < 7) {
            issue_chunk(ck + 1, buf ^ 1);
            asm volatile("cp.async.wait_group 1;" ::: "memory");
        } else {
            asm volatile("cp.async.wait_group 0;" ::: "memory");
        }
        __syncthreads();
        uint32_t base = sb + buf*BUF;
        #pragma unroll
        for (int ks = 0; ks < 32; ks += 16) {
            uint32_t ah[2][4], al[2][4], bh[2][4], bl[2][4];
            #pragma unroll
            for (int mi = 0; mi < 2; mi++) {
                uint32_t aa = base + AHo + (uint32_t)((arow + mi*16)*80 + (ks + acol8)*2);
                ldsm_x4(ah[mi], aa);
                ldsm_x4(al[mi], aa + (ALo - AHo));
            }
            #pragma unroll
            for (int p = 0; p < 2; p++) {
                uint32_t ba = base + BHo + (uint32_t)((brow + p*16)*80 + (ks + bcol8)*2);
                ldsm_x4(bh[p], ba);
                ldsm_x4(bl[p], ba + (BLo - BHo));
            }
            #pragma unroll
            for (int mi = 0; mi < 2; mi++)
                #pragma unroll
                for (int ni = 0; ni < 4; ni++) {
                    const uint32_t* bhp = &bh[ni >> 1][(ni & 1)*2];
                    const uint32_t* blp = &bl[ni >> 1][(ni & 1)*2];
                    mma16816(acc[mi][ni], ah[mi], bhp);
                    mma16816(acc[mi][ni], ah[mi], blp);
                    mma16816(acc[mi][ni], al[mi], bhp);
                }
        }
        __syncthreads();
    }

    // stage transposed: Ct[ch_local][tok_local] (overlays cp.async buffers)
    #pragma unroll
    for (int mi = 0; mi < 2; mi++)
        #pragma unroll
        for (int ni = 0; ni < 4; ni++) {
            int ml = wm + mi*16 + (lane >> 2);
            int nl = wn + ni*8 + 2*(lane & 3);
            Ct[nl][ml]       = acc[mi][ni][0];
            Ct[nl+1][ml]     = acc[mi][ni][1];
            Ct[nl][ml+8]     = acc[mi][ni][2];
            Ct[nl+1][ml+8]   = acc[mi][ni][3];
        }
    __syncthreads();

    int bb = m0 / NTOK, ptok = m0 % NTOK;
    int ch = tid >> 2, tg = tid & 3;
    float bias = d_bcomb[n0 + ch];
    size_t rowb = (size_t)(bb*CHN + n0 + ch) * NTOK + ptok;
    #pragma unroll
    for (int j = 0; j < 8; j++) {
        int tl = tg*32 + j*4;
        float4 v = *(float4*)&Ct[ch][tl];
        *(float4*)&out[rowb + tl] = make_float4(v.x+bias, v.y+bias, v.z+bias, v.w+bias);
    }
}

extern "C" void kernel_launch(void* const* d_in, const int* in_sizes, int n_in,
                              void* d_out, int out_size) {
    const float* x    = (const float*)d_in[0];
    const float* wq   = (const float*)d_in[1];
    const float* wk   = (const float*)d_in[2];
    const float* wv   = (const float*)d_in[3];
    const float* wo   = (const float*)d_in[4];
    const float* bo   = (const float*)d_in[5];
    const float* proj = (const float*)d_in[6];
    const float* wp   = (const float*)d_in[7];
    const float* bp   = (const float*)d_in[8];
    float* out = (float*)d_out;

    cudaFuncSetAttribute(qkv_mms, cudaFuncAttributeMaxDynamicSharedMemorySize, 61440);
    cudaFuncSetAttribute(out_mms, cudaFuncAttributeMaxDynamicSharedMemorySize, 61440);
    cudaFuncSetAttribute(k_mms, cudaFuncAttributeMaxDynamicSharedMemorySize, 76800);
    cudaFuncSetAttribute(q_mms, cudaFuncAttributeMaxDynamicSharedMemorySize, 77824);

    init_k<<<768, 256>>>();
    conv_w<<<dim3(256, 3), 256>>>(wq, wk, wv);
    wcomb_k<<<256, 256>>>(wo, bo, wp, bp);
    xt_k<<<dim3(288, 8, 4), 256>>>(x);
    vsum_k<<<BH, 32>>>(wv);
    qkv_mms<<<dim3(288, 4, 3), 256, 61440>>>();
    k_mms<<<dim3(8, BH), 256, 76800>>>(proj);
    k_final<<<BH, 128>>>();
    q_mms<<<dim3(18, BH), 256, 77824>>>(proj);
    out_mms<<<dim3(288, 4), 256, 61440>>>(out);
}